// round 9
// baseline (speedup 1.0000x reference)
#include <cuda_runtime.h>
#include <cuda_bf16.h>
#include <math.h>
#include <stdint.h>

#define HWSZ 16384
#define WD 128
#define NN 8
#define CCH 64
#define C3 192
#define HIDC 170
#define HID2 340
#define NHEADS 4

// ---------------- scratch (device globals; allocation is banned) ----------------
__device__ uint32_t g_lnp[(size_t)NN * 32 * HWSZ];     // packed bf16 branch intermediate
__device__ uint32_t g_lnp2[(size_t)NN * 32 * HWSZ];    // packed bf16 LN output (fused epilogues)
__device__ uint32_t g_bufAp[(size_t)NN * 170 * HWSZ];
__device__ uint32_t g_bufBp[(size_t)NN * 96 * HWSZ];
__device__ float g_attn[NN * NHEADS * 16 * 16];
__device__ float g_part[512 * 288];
__device__ uint32_t g_wp[50176];

// weight-pack offsets (words)
#define WP_SCIN  0
#define WP_SCOUT 18432
#define WP_MQKV  24576
#define WP_MPROJ 30720
#define WP_GIN   32768
#define WP_GOUT  43648
#define WP_TOTAL 49280

// ---------------- helpers ----------------
__device__ __forceinline__ void mma_tf32(float4& d,
                                         uint32_t a0, uint32_t a1, uint32_t a2, uint32_t a3,
                                         uint32_t b0, uint32_t b1) {
    asm volatile(
        "mma.sync.aligned.m16n8k8.row.col.f32.tf32.tf32.f32 "
        "{%0,%1,%2,%3}, {%4,%5,%6,%7}, {%8,%9}, {%0,%1,%2,%3};\n"
        : "+f"(d.x), "+f"(d.y), "+f"(d.z), "+f"(d.w)
        : "r"(a0), "r"(a1), "r"(a2), "r"(a3), "r"(b0), "r"(b1));
}
__device__ __forceinline__ void mma_bf16(float4& d,
                                         uint32_t a0, uint32_t a1, uint32_t a2, uint32_t a3,
                                         uint32_t b0, uint32_t b1) {
    asm volatile(
        "mma.sync.aligned.m16n8k16.row.col.f32.bf16.bf16.f32 "
        "{%0,%1,%2,%3}, {%4,%5,%6,%7}, {%8,%9}, {%0,%1,%2,%3};\n"
        : "+f"(d.x), "+f"(d.y), "+f"(d.z), "+f"(d.w)
        : "r"(a0), "r"(a1), "r"(a2), "r"(a3), "r"(b0), "r"(b1));
}
__device__ __forceinline__ uint32_t pack_bf16(float lo, float hi) {
    __nv_bfloat162 h = __floats2bfloat162_rn(lo, hi);
    return *(uint32_t*)&h;
}
__device__ __forceinline__ float2 upk(uint32_t w) {
    __nv_bfloat162 h = *(__nv_bfloat162*)&w;
    return __bfloat1622float2(h);
}
__device__ __forceinline__ uint32_t hfma2_bf(uint32_t a, uint32_t b, uint32_t c) {
    __nv_bfloat162 r = __hfma2(*(__nv_bfloat162*)&a, *(__nv_bfloat162*)&b, *(__nv_bfloat162*)&c);
    return *(uint32_t*)&r;
}
__device__ __forceinline__ uint4 uz4(const uint32_t* p, bool valid) {
    return valid ? *(const uint4*)p : make_uint4(0u, 0u, 0u, 0u);
}

// ---------------- single fused weight pack ----------------
__device__ __forceinline__ uint32_t pack_one(const float* w, int m, int k2,
                                             int KC2, int TAPS, int KTOT2) {
    if (k2 >= KTOT2) return 0u;
    int KCfull = KC2 * 2;
    int i0, i1;
    if (TAPS == 1) { i0 = m * KCfull + 2 * k2; i1 = i0 + 1; }
    else {
        int dt = k2 / KC2, ic2 = k2 % KC2;
        i0 = (m * KCfull + 2 * ic2) * 3 + dt;
        i1 = (m * KCfull + 2 * ic2 + 1) * 3 + dt;
    }
    return pack_bf16(w[i0], w[i1]);
}

__global__ __launch_bounds__(256) void wpack_all(const float* __restrict__ scin,
                                                 const float* __restrict__ scout,
                                                 const float* __restrict__ mqkv,
                                                 const float* __restrict__ mproj,
                                                 const float* __restrict__ gin,
                                                 const float* __restrict__ gout,
                                                 uint32_t* __restrict__ dst) {
    int t = blockIdx.x * 256 + threadIdx.x;
    if (t >= WP_TOTAL) return;
    uint32_t v;
    if (t < WP_SCOUT) {
        int u = t - WP_SCIN;      v = pack_one(scin, u / 96, u % 96, 32, 3, 96);
    } else if (t < WP_MQKV) {
        int u = t - WP_SCOUT;     v = pack_one(scout, u / 96, u % 96, 32, 3, 96);
    } else if (t < WP_MPROJ) {
        int u = t - WP_MQKV;      v = pack_one(mqkv, u / 32, u % 32, 32, 1, 32);
    } else if (t < WP_GIN) {
        int u = t - WP_MPROJ;     v = pack_one(mproj, u / 32, u % 32, 32, 1, 32);
    } else if (t < WP_GOUT) {
        int u = t - WP_GIN;       v = pack_one(gin, u / 32, u % 32, 32, 1, 32);
    } else {
        int u = t - WP_GOUT;      v = pack_one(gout, u / 88, u % 88, 85, 1, 85);
    }
    dst[t] = v;
}

// ---------------- LayerNorm -> packed bf16 (branch 1 only) ----------------
__global__ __launch_bounds__(256) void ln_p(const float* __restrict__ x,
                                            const float* __restrict__ w,
                                            const float* __restrict__ b,
                                            uint32_t* __restrict__ outp) {
    int idx = blockIdx.x * 256 + threadIdx.x;
    int n = idx >> 14, hw = idx & (HWSZ - 1);
    const float* px = x + (size_t)n * CCH * HWSZ + hw;
    float v[CCH];
    float s = 0.f;
#pragma unroll
    for (int c = 0; c < CCH; c++) { v[c] = px[(size_t)c * HWSZ]; s += v[c]; }
    float mu = s * (1.f / CCH);
    float ss = 0.f;
#pragma unroll
    for (int c = 0; c < CCH; c++) { float d = v[c] - mu; ss = fmaf(d, d, ss); }
    float inv = rsqrtf(ss * (1.f / CCH) + 1e-5f);
    uint32_t* po = outp + (size_t)n * 32 * HWSZ + hw;
#pragma unroll
    for (int c2 = 0; c2 < 32; c2++) {
        float a = (v[2 * c2] - mu) * inv * w[2 * c2] + b[2 * c2];
        float c_ = (v[2 * c2 + 1] - mu) * inv * w[2 * c2 + 1] + b[2 * c2 + 1];
        po[(size_t)c2 * HWSZ] = pack_bf16(a, c_);
    }
}

// ---------------- bf16 tensor-core pointwise conv, cp.async double-buffered ----------------
// LNOUT (requires MTILE=64, M=64): epilogue also computes per-pixel LayerNorm of
// (acc+bias+resid) and writes packed bf16 to lnoutp.
template <int KC2, int TAPS, int MTILE, bool OUTBF, bool LNOUT>
__global__ __launch_bounds__(256, 2) void pconv5(const uint32_t* __restrict__ inp,
                                                 const uint32_t* __restrict__ wp,
                                                 const float* __restrict__ bias,
                                                 const float* __restrict__ resid,
                                                 float* __restrict__ outf,
                                                 uint32_t* __restrict__ outp, int M,
                                                 const float* __restrict__ normw,
                                                 const float* __restrict__ normb,
                                                 uint32_t* __restrict__ lnoutp) {
    constexpr int KTOT2 = KC2 * TAPS;
    constexpr int NCHUNK = (KTOT2 + 7) / 8;
    constexpr int KP2 = NCHUNK * 8;
    constexpr int PTILE = (MTILE == 64) ? 256 : 128;
    constexpr int XSW = PTILE + 8;
    constexpr int WSW = 12;
    constexpr int MW = MTILE / 32;
    __shared__ uint32_t sX[2][8 * XSW];
    __shared__ uint32_t sW[2][MTILE * WSW];
    __shared__ float lnS[2][256];
    __shared__ float lnQ[2][256];

    const int tid = threadIdx.x;
    const int lane = tid & 31, warp = tid >> 5;
    const int mw = warp % MW, pw = warp / MW;
    const int mbase = blockIdx.y * MTILE;
    const int pix0 = blockIdx.x * PTILE;
    const int n = blockIdx.z, b = n >> 2, t = n & 3;
    const int l3 = lane & 3, r = lane >> 2;

    float4 acc[2][8];
#pragma unroll
    for (int mt = 0; mt < 2; mt++)
#pragma unroll
        for (int j = 0; j < 8; j++) acc[mt][j] = make_float4(0.f, 0.f, 0.f, 0.f);

    auto stageX = [&](int c0, int bufi) {
#pragma unroll
        for (int i = tid; i < 2 * PTILE; i += 256) {
            int row = i / (PTILE / 4), p4 = (i % (PTILE / 4)) << 2;
            int k2 = c0 * 8 + row;
            const uint32_t* sp = inp;
            int sz = 0;
            if (k2 < KTOT2) {
                int ic2, tt;
                if (TAPS == 1) { ic2 = k2; tt = t; }
                else { int dt = k2 / KC2; ic2 = k2 - dt * KC2; tt = t + dt - 1; }
                if (tt >= 0 && tt < 4) {
                    sp = &inp[((size_t)(b * 4 + tt) * KC2 + ic2) * HWSZ + pix0 + p4];
                    sz = 16;
                }
            }
            uint32_t d = (uint32_t)__cvta_generic_to_shared(&sX[bufi][row * XSW + p4]);
            asm volatile("cp.async.cg.shared.global [%0],[%1],16,%2;\n"
                         :: "r"(d), "l"(sp), "r"(sz));
        }
    };
    auto stageW = [&](int c0, int bufi) {
#pragma unroll
        for (int i = tid; i < MTILE * 2; i += 256) {
            int m = i >> 1, q = i & 1;
            int gk2 = c0 * 8 + q * 4;
            int sz = (mbase + m < M) ? 16 : 0;
            const uint32_t* sp = (sz > 0) ? &wp[(size_t)(mbase + m) * KP2 + gk2] : wp;
            uint32_t d = (uint32_t)__cvta_generic_to_shared(&sW[bufi][m * WSW + q * 4]);
            asm volatile("cp.async.cg.shared.global [%0],[%1],16,%2;\n"
                         :: "r"(d), "l"(sp), "r"(sz));
        }
    };

    stageX(0, 0); stageW(0, 0);
    asm volatile("cp.async.commit_group;\n");
    int buf = 0;
    for (int c = 0; c < NCHUNK; c++) {
        if (c + 1 < NCHUNK) {
            stageX(c + 1, buf ^ 1); stageW(c + 1, buf ^ 1);
            asm volatile("cp.async.commit_group;\n");
            asm volatile("cp.async.wait_group 1;\n");
        } else {
            asm volatile("cp.async.wait_group 0;\n");
        }
        __syncthreads();
        const uint32_t* X = sX[buf];
        const uint32_t* W = sW[buf];
        const int ar = mw * 32 + r;
        uint32_t a[2][4];
#pragma unroll
        for (int mt = 0; mt < 2; mt++) {
            int wb = (ar + mt * 16) * WSW;
            a[mt][0] = W[wb + l3];
            a[mt][1] = W[wb + 8 * WSW + l3];
            a[mt][2] = W[wb + l3 + 4];
            a[mt][3] = W[wb + 8 * WSW + l3 + 4];
        }
        const int bc = pw * 64 + r;
#pragma unroll
        for (int nt = 0; nt < 8; nt++) {
            uint32_t b0 = X[l3 * XSW + bc + nt * 8];
            uint32_t b1 = X[(l3 + 4) * XSW + bc + nt * 8];
            mma_bf16(acc[0][nt], a[0][0], a[0][1], a[0][2], a[0][3], b0, b1);
            mma_bf16(acc[1][nt], a[1][0], a[1][1], a[1][2], a[1][3], b0, b1);
        }
        __syncthreads();
        buf ^= 1;
    }

    const int r0 = mw * 32 + r;
    const int cb = pw * 64 + (l3 << 1);

    if (LNOUT) {
        // full-channel block: fp32 out + fused per-pixel LayerNorm -> packed bf16
        float bi[2][2], nw[2][2], nbv[2][2];
#pragma unroll
        for (int mt = 0; mt < 2; mt++)
#pragma unroll
            for (int half = 0; half < 2; half++) {
                int oc = r0 + mt * 16 + half * 8;
                bi[mt][half] = bias ? bias[oc] : 0.f;
                nw[mt][half] = normw[oc];
                nbv[mt][half] = normb[oc];
            }
#pragma unroll
        for (int j = 0; j < 8; j++) {
            int p0 = cb + j * 8;
            float s0 = 0.f, q0 = 0.f, s1 = 0.f, q1 = 0.f;
#pragma unroll
            for (int mt = 0; mt < 2; mt++)
#pragma unroll
                for (int half = 0; half < 2; half++) {
                    int oc = r0 + mt * 16 + half * 8;
                    size_t ob = ((size_t)n * 64 + oc) * HWSZ + pix0 + p0;
                    float vx = (half ? acc[mt][j].z : acc[mt][j].x) + bi[mt][half];
                    float vy = (half ? acc[mt][j].w : acc[mt][j].y) + bi[mt][half];
                    float2 rv = *(const float2*)&resid[ob];
                    vx += rv.x; vy += rv.y;
                    *(float2*)&outf[ob] = make_float2(vx, vy);
                    if (half) { acc[mt][j].z = vx; acc[mt][j].w = vy; }
                    else { acc[mt][j].x = vx; acc[mt][j].y = vy; }
                    s0 += vx; q0 = fmaf(vx, vx, q0);
                    s1 += vy; q1 = fmaf(vy, vy, q1);
                }
#pragma unroll
            for (int msk = 4; msk <= 16; msk <<= 1) {
                s0 += __shfl_xor_sync(0xffffffffu, s0, msk);
                q0 += __shfl_xor_sync(0xffffffffu, q0, msk);
                s1 += __shfl_xor_sync(0xffffffffu, s1, msk);
                q1 += __shfl_xor_sync(0xffffffffu, q1, msk);
            }
            if (r == 0) {
                lnS[mw][p0] = s0; lnQ[mw][p0] = q0;
                lnS[mw][p0 + 1] = s1; lnQ[mw][p0 + 1] = q1;
            }
        }
        __syncthreads();
#pragma unroll
        for (int j = 0; j < 8; j++) {
            int p0 = cb + j * 8;
            float m0 = (lnS[0][p0] + lnS[1][p0]) * (1.f / 64);
            float v0 = (lnQ[0][p0] + lnQ[1][p0]) * (1.f / 64) - m0 * m0;
            float i0 = rsqrtf(fmaxf(v0, 0.f) + 1e-5f);
            float m1 = (lnS[0][p0 + 1] + lnS[1][p0 + 1]) * (1.f / 64);
            float v1 = (lnQ[0][p0 + 1] + lnQ[1][p0 + 1]) * (1.f / 64) - m1 * m1;
            float i1 = rsqrtf(fmaxf(v1, 0.f) + 1e-5f);
#pragma unroll
            for (int mt = 0; mt < 2; mt++)
#pragma unroll
                for (int half = 0; half < 2; half++) {
                    int oc = r0 + mt * 16 + half * 8;
                    float vx = half ? acc[mt][j].z : acc[mt][j].x;
                    float vy = half ? acc[mt][j].w : acc[mt][j].y;
                    float nx = (vx - m0) * i0 * nw[mt][half] + nbv[mt][half];
                    float ny = (vy - m1) * i1 * nw[mt][half] + nbv[mt][half];
                    float qx = __shfl_down_sync(0xffffffffu, nx, 4);
                    float qy = __shfl_down_sync(0xffffffffu, ny, 4);
                    if (!(r & 1)) {
                        uint2 st;
                        st.x = pack_bf16(nx, qx);
                        st.y = pack_bf16(ny, qy);
                        *(uint2*)&lnoutp[((size_t)n * 32 + (oc >> 1)) * HWSZ + pix0 + p0] = st;
                    }
                }
        }
    } else if (OUTBF) {
        const int M2 = M >> 1;
#pragma unroll
        for (int mt = 0; mt < 2; mt++)
#pragma unroll
            for (int half = 0; half < 2; half++) {
                int oc = mbase + r0 + mt * 16 + half * 8;
                float bi = (bias && oc < M) ? bias[oc] : 0.f;
#pragma unroll
                for (int j = 0; j < 8; j++) {
                    float vx = (half ? acc[mt][j].z : acc[mt][j].x) + bi;
                    float vy = (half ? acc[mt][j].w : acc[mt][j].y) + bi;
                    float qx = __shfl_down_sync(0xffffffffu, vx, 4);
                    float qy = __shfl_down_sync(0xffffffffu, vy, 4);
                    if (!(r & 1) && oc < M) {
                        uint2 st;
                        st.x = pack_bf16(vx, qx);
                        st.y = pack_bf16(vy, qy);
                        *(uint2*)&outp[((size_t)n * M2 + (oc >> 1)) * HWSZ + pix0 + cb + j * 8] = st;
                    }
                }
            }
    } else {
#pragma unroll
        for (int mt = 0; mt < 2; mt++)
#pragma unroll
            for (int half = 0; half < 2; half++) {
                int oc = mbase + r0 + mt * 16 + half * 8;
                if (oc >= M) continue;
                float bi = bias ? bias[oc] : 0.f;
                size_t ob = ((size_t)n * M + oc) * HWSZ + pix0 + cb;
#pragma unroll
                for (int j = 0; j < 8; j++) {
                    float2 v = (half == 0)
                        ? make_float2(acc[mt][j].x + bi, acc[mt][j].y + bi)
                        : make_float2(acc[mt][j].z + bi, acc[mt][j].w + bi);
                    if (resid) {
                        float2 rv = *(const float2*)&resid[ob + j * 8];
                        v.x += rv.x; v.y += rv.y;
                    }
                    *(float2*)&outf[ob + j * 8] = v;
                }
            }
    }
}

// ---------------- depthwise 3x3 on packed bf16 (MDTA branch only) ----------------
template <int DIL>
__global__ __launch_bounds__(256) void dw3x3_p(const uint32_t* __restrict__ inp,
                                               const float* __restrict__ w,
                                               const float* __restrict__ bias,
                                               uint32_t* __restrict__ outp, int CH2) {
    size_t idx = (size_t)blockIdx.x * 256 + threadIdx.x;
    size_t tot = (size_t)NN * CH2 * 4096;
    if (idx >= tot) return;
    int q = (int)(idx & 4095);
    int nc2 = (int)(idx >> 12);
    int c2 = nc2 % CH2;
    int h = q >> 5, x4 = (q & 31) << 2;
    const uint32_t* src = inp + (size_t)nc2 * HWSZ;
    float wl[9], wh[9];
#pragma unroll
    for (int i = 0; i < 9; i++) {
        wl[i] = w[(2 * c2) * 9 + i];
        wh[i] = w[(2 * c2 + 1) * 9 + i];
    }
    float bl = bias ? bias[2 * c2] : 0.f;
    float bh = bias ? bias[2 * c2 + 1] : 0.f;
    float al[4] = {bl, bl, bl, bl}, ah[4] = {bh, bh, bh, bh};
#pragma unroll
    for (int ki = 0; ki < 3; ki++) {
        int hh = h + (ki - 1) * DIL;
        if ((unsigned)hh >= 128u) continue;
        const uint32_t* row = src + hh * WD;
        uint32_t wbuf[12];
        *(uint4*)&wbuf[0] = uz4(row + x4 - 4, x4 >= 4);
        *(uint4*)&wbuf[4] = *(const uint4*)(row + x4);
        *(uint4*)&wbuf[8] = uz4(row + x4 + 4, x4 < 124);
        float flo[12], fhi[12];
#pragma unroll
        for (int i = 0; i < 12; i++) { float2 f = upk(wbuf[i]); flo[i] = f.x; fhi[i] = f.y; }
#pragma unroll
        for (int kj = 0; kj < 3; kj++) {
            float wvl = wl[ki * 3 + kj], wvh = wh[ki * 3 + kj];
            int off = 4 + (kj - 1) * DIL;
#pragma unroll
            for (int p = 0; p < 4; p++) {
                al[p] = fmaf(flo[off + p], wvl, al[p]);
                ah[p] = fmaf(fhi[off + p], wvh, ah[p]);
            }
        }
    }
    uint4 st;
    st.x = pack_bf16(al[0], ah[0]); st.y = pack_bf16(al[1], ah[1]);
    st.z = pack_bf16(al[2], ah[2]); st.w = pack_bf16(al[3], ah[3]);
    *(uint4*)&outp[(size_t)nc2 * HWSZ + q * 4] = st;
}

// ---------------- fused depthwise3x3 + SWSA window attention ----------------
// dynamic smem layout (bytes):
//   pat  @0      : uint32[32*10*16]  = 20480
//   qsh  @20480  : float [4*64*17]   = 17408
//   kshB @37888  : float [4*16*68]   = 17408
//   vsh  @55296  : uint32[4*32*17]   = 8704
//   bsh  @64000  : float [900]       = 3600    total 67600
#define SWSA5_SMEM 67600
__global__ __launch_bounds__(256, 2) void swsa5(const uint32_t* __restrict__ qkvp,
                                                const float* __restrict__ dww,
                                                const float* __restrict__ dwb,
                                                const float* __restrict__ rpb,
                                                uint32_t* __restrict__ outp) {
    extern __shared__ char smem_raw[];
    uint32_t* pat = (uint32_t*)smem_raw;
    float* qsh = (float*)(smem_raw + 20480);
    float* kshB = (float*)(smem_raw + 37888);
    uint32_t* vsh = (uint32_t*)(smem_raw + 55296);
    float* bsh = (float*)(smem_raw + 64000);

    const int tid = threadIdx.x;
    const int lane = tid & 31, warp = tid >> 5;
    const int n = blockIdx.x >> 8;
    const int wrem = blockIdx.x & 255;
    const int wi = wrem >> 4, wj = wrem & 15;
    const int wbase = (wi * 8) * WD + wj * 8;
    const size_t nb = (size_t)n * 96 * HWSZ;

    for (int i = tid; i < 900; i += 256) bsh[(i & 3) * 225 + (i >> 2)] = rpb[i];

    // ---- dw3x3 on 10x10 halo patch, one qkv group (q/k/v) at a time ----
    for (int g = 0; g < 3; g++) {
        __syncthreads();
        for (int u = tid; u < 1280; u += 256) {
            int c2py = u >> 2, q4i = u & 3;
            int c2l = c2py / 10, py = c2py - c2l * 10;
            int imrow = wi * 8 - 1 + py;
            int gx = wj * 8 - 4 + q4i * 4;
            uint4 v = make_uint4(0u, 0u, 0u, 0u);
            if ((unsigned)imrow < 128u && (unsigned)gx < 125u)
                v = *(const uint4*)&qkvp[nb + (size_t)(g * 32 + c2l) * HWSZ + imrow * WD + gx];
            *(uint4*)&pat[(c2l * 10 + py) * 16 + q4i * 4] = v;
        }
        __syncthreads();
        for (int u = tid; u < 2048; u += 256) {
            int c2l = u >> 6, p = u & 63;
            int qi = p >> 3, qj = p & 7;
            int ch0 = (g * 32 + c2l) * 2;
            float lo = dwb[ch0], hi = dwb[ch0 + 1];
            const float* w0 = &dww[ch0 * 9];
#pragma unroll
            for (int dy = 0; dy < 3; dy++)
#pragma unroll
                for (int dx = 0; dx < 3; dx++) {
                    float2 f = upk(pat[(c2l * 10 + qi + dy) * 16 + 3 + qj + dx]);
                    lo = fmaf(f.x, w0[dy * 3 + dx], lo);
                    hi = fmaf(f.y, w0[9 + dy * 3 + dx], hi);
                }
            int head = c2l >> 3, d0 = (c2l & 7) * 2;
            if (g == 0) {
                qsh[(head * 64 + p) * 17 + d0] = lo * 0.25f;
                qsh[(head * 64 + p) * 17 + d0 + 1] = hi * 0.25f;
            } else if (g == 1) {
                kshB[(head * 16 + d0) * 68 + p] = lo;
                kshB[(head * 16 + d0 + 1) * 68 + p] = hi;
            } else {
                __nv_bfloat16* v16 = (__nv_bfloat16*)vsh;
                int k2 = p >> 1, hf = p & 1;
                v16[((head * 32 + k2) * 17 + d0) * 2 + hf] = __float2bfloat16(lo);
                v16[((head * 32 + k2) * 17 + d0 + 1) * 2 + hf] = __float2bfloat16(hi);
            }
        }
    }
    __syncthreads();

    // ---- attention ----
    const int head = warp >> 1;
    const int qbase = (warp & 1) * 32;
    const int r = lane >> 2;
    const int l3 = lane & 3;
    const int kj2 = l3 * 2;

    float4 S[2][8];
#pragma unroll
    for (int mt = 0; mt < 2; mt++)
#pragma unroll
        for (int nt = 0; nt < 8; nt++) S[mt][nt] = make_float4(0.f, 0.f, 0.f, 0.f);
    const float* Q = &qsh[head * 64 * 17];
    const float* K = &kshB[head * 16 * 68];
#pragma unroll
    for (int kb = 0; kb < 16; kb += 8) {
        const int kc = kb + l3;
        uint32_t a[2][4];
#pragma unroll
        for (int mt = 0; mt < 2; mt++) {
            int ar = qbase + mt * 16 + r;
            a[mt][0] = __float_as_uint(Q[ar * 17 + kc]);
            a[mt][1] = __float_as_uint(Q[(ar + 8) * 17 + kc]);
            a[mt][2] = __float_as_uint(Q[ar * 17 + kc + 4]);
            a[mt][3] = __float_as_uint(Q[(ar + 8) * 17 + kc + 4]);
        }
#pragma unroll
        for (int nt = 0; nt < 8; nt++) {
            uint32_t b0 = __float_as_uint(K[(kb + l3) * 68 + nt * 8 + r]);
            uint32_t b1 = __float_as_uint(K[(kb + 4 + l3) * 68 + nt * 8 + r]);
            mma_tf32(S[0][nt], a[0][0], a[0][1], a[0][2], a[0][3], b0, b1);
            mma_tf32(S[1][nt], a[1][0], a[1][1], a[1][2], a[1][3], b0, b1);
        }
    }

    int Aq[2][2];
#pragma unroll
    for (int mt = 0; mt < 2; mt++)
#pragma unroll
        for (int rh = 0; rh < 2; rh++) {
            int q = qbase + mt * 16 + r + rh * 8;
            Aq[mt][rh] = ((q >> 3) + 7) * 15 + (q & 7) + 7;
        }
    const float* bh = &bsh[head * 225];
    float den[2][2] = {{0.f, 0.f}, {0.f, 0.f}};
    uint32_t eb[2][8][2], ub[2][8][2];
#pragma unroll
    for (int mt = 0; mt < 2; mt++)
#pragma unroll
        for (int nt = 0; nt < 8; nt++) {
            int bc = nt * 15 + kj2;
            int i0 = Aq[mt][0] - bc;
            int i1 = Aq[mt][1] - bc;
            float4 s = S[mt][nt];
            float s0 = s.x + bh[i0], s1 = s.y + bh[i0 - 1];
            float s2 = s.z + bh[i1], s3 = s.w + bh[i1 - 1];
            float e0 = __expf(s0), e1 = __expf(s1), e2 = __expf(s2), e3 = __expf(s3);
            den[mt][0] += e0 + e1;
            den[mt][1] += e2 + e3;
            eb[mt][nt][0] = pack_bf16(e0, e1);
            eb[mt][nt][1] = pack_bf16(e2, e3);
            float u0 = fmaxf(s0, 0.f); u0 = 0.75f * u0 * u0;
            float u1 = fmaxf(s1, 0.f); u1 = 0.75f * u1 * u1;
            float u2 = fmaxf(s2, 0.f); u2 = 0.75f * u2 * u2;
            float u3 = fmaxf(s3, 0.f); u3 = 0.75f * u3 * u3;
            ub[mt][nt][0] = pack_bf16(u0, u1);
            ub[mt][nt][1] = pack_bf16(u2, u3);
        }
    uint32_t w2[2][2];
#pragma unroll
    for (int mt = 0; mt < 2; mt++)
#pragma unroll
        for (int rh = 0; rh < 2; rh++) {
            float dv = den[mt][rh];
            dv += __shfl_xor_sync(0xffffffffu, dv, 1);
            dv += __shfl_xor_sync(0xffffffffu, dv, 2);
            float wsm = 0.25f / dv;
            w2[mt][rh] = pack_bf16(wsm, wsm);
        }

    float4 O[2][2];
#pragma unroll
    for (int mt = 0; mt < 2; mt++)
#pragma unroll
        for (int v = 0; v < 2; v++) O[mt][v] = make_float4(0.f, 0.f, 0.f, 0.f);
    const uint32_t* V = &vsh[head * 32 * 17];
#pragma unroll
    for (int mt = 0; mt < 2; mt++)
#pragma unroll
        for (int t = 0; t < 4; t++) {
            uint32_t a0 = hfma2_bf(eb[mt][2 * t][0], w2[mt][0], ub[mt][2 * t][0]);
            uint32_t a1 = hfma2_bf(eb[mt][2 * t][1], w2[mt][1], ub[mt][2 * t][1]);
            uint32_t a2 = hfma2_bf(eb[mt][2 * t + 1][0], w2[mt][0], ub[mt][2 * t + 1][0]);
            uint32_t a3 = hfma2_bf(eb[mt][2 * t + 1][1], w2[mt][1], ub[mt][2 * t + 1][1]);
#pragma unroll
            for (int v = 0; v < 2; v++) {
                uint32_t b0 = V[(t * 8 + l3) * 17 + v * 8 + r];
                uint32_t b1 = V[(t * 8 + 4 + l3) * 17 + v * 8 + r];
                mma_bf16(O[mt][v], a0, a1, a2, a3, b0, b1);
            }
        }

    __syncthreads();
    float* osh = qsh;
#pragma unroll
    for (int mt = 0; mt < 2; mt++)
#pragma unroll
        for (int v = 0; v < 2; v++) {
            int qrow = qbase + mt * 16 + r;
            int c0 = head * 16 + v * 8 + kj2;
            osh[c0 * 68 + qrow] = O[mt][v].x;
            osh[(c0 + 1) * 68 + qrow] = O[mt][v].y;
            osh[c0 * 68 + qrow + 8] = O[mt][v].z;
            osh[(c0 + 1) * 68 + qrow + 8] = O[mt][v].w;
        }
    __syncthreads();
    for (int i = tid; i < 512; i += 256) {
        int c2 = i >> 4, q4 = i & 15;
        int q0 = q4 * 4;
        int goff = wbase + (q4 >> 1) * WD + (q4 & 1) * 4;
        const float* lo = &osh[(2 * c2) * 68 + q0];
        const float* hi = &osh[(2 * c2 + 1) * 68 + q0];
        uint4 st;
        st.x = pack_bf16(lo[0], hi[0]); st.y = pack_bf16(lo[1], hi[1]);
        st.z = pack_bf16(lo[2], hi[2]); st.w = pack_bf16(lo[3], hi[3]);
        *(uint4*)&outp[((size_t)n * 32 + c2) * HWSZ + goff] = st;
    }
}

// ---------------- MDTA gram partials (packed input) ----------------
__global__ __launch_bounds__(256) void mdta_gram_p(const uint32_t* __restrict__ qkvp,
                                                   float* __restrict__ part) {
    int blk = blockIdx.x;
    int seg = blk & 15;
    int nh = blk >> 4;
    int n = nh >> 2, head = nh & 3;
    int c = threadIdx.x >> 4, d = threadIdx.x & 15;
    __shared__ float qsh[16 * 129];
    __shared__ float ksh2[16 * 129];
    float acc = 0.f, qq = 0.f, kk2 = 0.f;
    const uint32_t* qb = qkvp + ((size_t)n * 96 + head * 8) * HWSZ;
    const uint32_t* kb = qkvp + ((size_t)n * 96 + 32 + head * 8) * HWSZ;
    int base0 = seg * 1024;
    for (int it = 0; it < 8; it++) {
        int base = base0 + it * 128;
        for (int i = threadIdx.x; i < 1024; i += 256) {
            int cc2 = i >> 7, j = i & 127;
            float2 fq = upk(qb[(size_t)cc2 * HWSZ + base + j]);
            qsh[(2 * cc2) * 129 + j] = fq.x;
            qsh[(2 * cc2 + 1) * 129 + j] = fq.y;
            float2 fk = upk(kb[(size_t)cc2 * HWSZ + base + j]);
            ksh2[(2 * cc2) * 129 + j] = fk.x;
            ksh2[(2 * cc2 + 1) * 129 + j] = fk.y;
        }
        __syncthreads();
#pragma unroll 8
        for (int j = 0; j < 128; j++) {
            float qv = qsh[c * 129 + j];
            float kv = ksh2[d * 129 + j];
            acc = fmaf(qv, kv, acc);
            if (d == 0) qq = fmaf(qv, qv, qq);
            if (c == 0) kk2 = fmaf(kv, kv, kk2);
        }
        __syncthreads();
    }
    float* pb = part + (size_t)blk * 288;
    pb[c * 16 + d] = acc;
    if (d == 0) pb[256 + c] = qq;
    if (c == 0) pb[272 + d] = kk2;
}

__global__ __launch_bounds__(256) void mdta_gram_reduce(const float* __restrict__ part,
                                                        const float* __restrict__ temp,
                                                        float* __restrict__ attn_out) {
    int nh = blockIdx.x;
    int n = nh >> 2, head = nh & 3;
    int tid = threadIdx.x;
    __shared__ float gram[256];
    __shared__ float qn[16], kn[16];
    float g = 0.f;
    for (int s = 0; s < 16; s++) g += part[(size_t)(nh * 16 + s) * 288 + tid];
    gram[tid] = g;
    if (tid < 16) {
        float qq = 0.f;
        for (int s = 0; s < 16; s++) qq += part[(size_t)(nh * 16 + s) * 288 + 256 + tid];
        qn[tid] = sqrtf(qq);
    } else if (tid < 32) {
        float kk = 0.f;
        for (int s = 0; s < 16; s++) kk += part[(size_t)(nh * 16 + s) * 288 + 272 + (tid - 16)];
        kn[tid - 16] = sqrtf(kk);
    }
    __syncthreads();
    if (tid < 16) {
        int r = tid;
        float tp = temp[head];
        float iq = 1.f / fmaxf(qn[r], 1e-12f);
        float rowv[16];
        float mx = -1e30f;
#pragma unroll
        for (int j = 0; j < 16; j++) {
            float a = gram[r * 16 + j] * iq / fmaxf(kn[j], 1e-12f) * tp;
            rowv[j] = a;
            mx = fmaxf(mx, a);
        }
        float den = 0.f;
#pragma unroll
        for (int j = 0; j < 16; j++) { float e = __expf(rowv[j] - mx); rowv[j] = e; den += e; }
        float inv = 1.f / den;
#pragma unroll
        for (int j = 0; j < 16; j++)
            attn_out[(((size_t)n * NHEADS + head) * 16 + r) * 16 + j] = rowv[j] * inv;
    }
}

// ---------------- MDTA: out = attn @ v (packed in/out) ----------------
__global__ __launch_bounds__(256) void mdta_out_p(const uint32_t* __restrict__ qkvp,
                                                  const float* __restrict__ attn,
                                                  uint32_t* __restrict__ outp) {
    __shared__ float ash[NHEADS * 256];
    int n = blockIdx.y;
    for (int i = threadIdx.x; i < NHEADS * 256; i += 256)
        ash[i] = attn[(size_t)n * NHEADS * 256 + i];
    __syncthreads();
    int hw = (blockIdx.x * 256 + threadIdx.x) * 4;
#pragma unroll
    for (int head = 0; head < NHEADS; head++) {
        float vv[16][4];
        const uint32_t* vb = qkvp + ((size_t)n * 96 + 64 + head * 8) * HWSZ + hw;
#pragma unroll
        for (int d2 = 0; d2 < 8; d2++) {
            uint4 wv = *(const uint4*)(vb + (size_t)d2 * HWSZ);
            const uint32_t* ws = &wv.x;
#pragma unroll
            for (int p = 0; p < 4; p++) {
                float2 f = upk(ws[p]);
                vv[2 * d2][p] = f.x;
                vv[2 * d2 + 1][p] = f.y;
            }
        }
#pragma unroll
        for (int c2 = 0; c2 < 8; c2++) {
            float slo[4] = {0.f, 0.f, 0.f, 0.f}, shi[4] = {0.f, 0.f, 0.f, 0.f};
            const float* alo = &ash[(head * 16 + 2 * c2) * 16];
            const float* ahi = &ash[(head * 16 + 2 * c2 + 1) * 16];
#pragma unroll
            for (int d = 0; d < 16; d++) {
                float wl = alo[d], wh = ahi[d];
#pragma unroll
                for (int p = 0; p < 4; p++) {
                    slo[p] = fmaf(wl, vv[d][p], slo[p]);
                    shi[p] = fmaf(wh, vv[d][p], shi[p]);
                }
            }
            uint4 st;
            st.x = pack_bf16(slo[0], shi[0]); st.y = pack_bf16(slo[1], shi[1]);
            st.z = pack_bf16(slo[2], shi[2]); st.w = pack_bf16(slo[3], shi[3]);
            *(uint4*)&outp[((size_t)n * 32 + head * 8 + c2) * HWSZ + hw] = st;
        }
    }
}

// ---------------- GDFN depthwise + gelu gate (packed in/out) ----------------
__global__ __launch_bounds__(256) void gdfn_p(const uint32_t* __restrict__ inp,
                                              const float* __restrict__ w1,
                                              const float* __restrict__ b1,
                                              const float* __restrict__ w2,
                                              const float* __restrict__ b2,
                                              uint32_t* __restrict__ outp) {
    size_t idx = (size_t)blockIdx.x * 256 + threadIdx.x;
    size_t tot = (size_t)NN * 85 * 4096;
    if (idx >= tot) return;
    int q = (int)(idx & 4095);
    int nc2 = (int)(idx >> 12);
    int c2 = nc2 % 85, n = nc2 / 85;
    int h = q >> 5, x4 = (q & 31) << 2;
    const uint32_t* s1 = inp + ((size_t)n * 170 + c2) * HWSZ;
    const uint32_t* s2 = inp + ((size_t)n * 170 + 85 + c2) * HWSZ;
    float w1l[9], w1h[9], w2l[9], w2h[9];
#pragma unroll
    for (int i = 0; i < 9; i++) {
        w1l[i] = w1[(2 * c2) * 9 + i]; w1h[i] = w1[(2 * c2 + 1) * 9 + i];
        w2l[i] = w2[(2 * c2) * 9 + i]; w2h[i] = w2[(2 * c2 + 1) * 9 + i];
    }
    float bal = b1[2 * c2], bah = b1[2 * c2 + 1];
    float bbl = b2[2 * c2], bbh = b2[2 * c2 + 1];
    float al[4] = {bal, bal, bal, bal}, ah[4] = {bah, bah, bah, bah};
    float bl[4] = {bbl, bbl, bbl, bbl}, bh[4] = {bbh, bbh, bbh, bbh};
#pragma unroll
    for (int ki = 0; ki < 3; ki++) {
        int hh = h + (ki - 1);
        if ((unsigned)hh >= 128u) continue;
        const uint32_t* r1 = s1 + hh * WD;
        const uint32_t* r2 = s2 + hh * WD;
        uint32_t wb1[12], wb2[12];
        *(uint4*)&wb1[0] = uz4(r1 + x4 - 4, x4 >= 4);
        *(uint4*)&wb1[4] = *(const uint4*)(r1 + x4);
        *(uint4*)&wb1[8] = uz4(r1 + x4 + 4, x4 < 124);
        *(uint4*)&wb2[0] = uz4(r2 + x4 - 4, x4 >= 4);
        *(uint4*)&wb2[4] = *(const uint4*)(r2 + x4);
        *(uint4*)&wb2[8] = uz4(r2 + x4 + 4, x4 < 124);
        float f1l[12], f1h[12], f2l[12], f2h[12];
#pragma unroll
        for (int i = 0; i < 12; i++) {
            float2 fa = upk(wb1[i]); f1l[i] = fa.x; f1h[i] = fa.y;
            float2 fb = upk(wb2[i]); f2l[i] = fb.x; f2h[i] = fb.y;
        }
#pragma unroll
        for (int kj = 0; kj < 3; kj++) {
            int off = 4 + (kj - 1);
            float v1l = w1l[ki * 3 + kj], v1h = w1h[ki * 3 + kj];
            float v2l = w2l[ki * 3 + kj], v2h = w2h[ki * 3 + kj];
#pragma unroll
            for (int p = 0; p < 4; p++) {
                al[p] = fmaf(f1l[off + p], v1l, al[p]);
                ah[p] = fmaf(f1h[off + p], v1h, ah[p]);
                bl[p] = fmaf(f2l[off + p], v2l, bl[p]);
                bh[p] = fmaf(f2h[off + p], v2h, bh[p]);
            }
        }
    }
    uint4 st;
    uint32_t* sp = &st.x;
#pragma unroll
    for (int p = 0; p < 4; p++) {
        float gl = 0.5f * al[p] * (1.f + erff(al[p] * 0.70710678118654752f));
        float gh = 0.5f * ah[p] * (1.f + erff(ah[p] * 0.70710678118654752f));
        sp[p] = pack_bf16(gl * bl[p], gh * bh[p]);
    }
    *(uint4*)&outp[(size_t)nc2 * HWSZ + q * 4] = st;
}

// ---------------- launch ----------------
extern "C" void kernel_launch(void* const* d_in, const int* in_sizes, int n_in,
                              void* d_out, int out_size) {
    const float* x       = (const float*)d_in[0];
    const float* norm_w  = (const float*)d_in[1];
    const float* norm_b  = (const float*)d_in[2];
    const float* s_cin_w = (const float*)d_in[3];
    const float* s_cin_b = (const float*)d_in[4];
    const float* s_dw_w  = (const float*)d_in[5];
    const float* s_dw_b  = (const float*)d_in[6];
    const float* s_rpb   = (const float*)d_in[7];
    const float* s_cout_w= (const float*)d_in[8];
    const float* s_cout_b= (const float*)d_in[9];
    const float* m_qkv_w = (const float*)d_in[10];
    const float* m_dw_w  = (const float*)d_in[11];
    const float* m_proj_w= (const float*)d_in[12];
    const float* m_temp  = (const float*)d_in[13];
    const float* g_in_w  = (const float*)d_in[14];
    const float* g_in_b  = (const float*)d_in[15];
    const float* g_d1_w  = (const float*)d_in[16];
    const float* g_d1_b  = (const float*)d_in[17];
    const float* g_d2_w  = (const float*)d_in[18];
    const float* g_d2_b  = (const float*)d_in[19];
    const float* g_out_w = (const float*)d_in[20];
    const float* g_out_b = (const float*)d_in[21];
    float* xo = (float*)d_out;

    uint32_t *lnp, *lnp2, *bufAp, *bufBp, *wp;
    float *attn, *part;
    cudaGetSymbolAddress((void**)&lnp, g_lnp);
    cudaGetSymbolAddress((void**)&lnp2, g_lnp2);
    cudaGetSymbolAddress((void**)&bufAp, g_bufAp);
    cudaGetSymbolAddress((void**)&bufBp, g_bufBp);
    cudaGetSymbolAddress((void**)&attn, g_attn);
    cudaGetSymbolAddress((void**)&part, g_part);
    cudaGetSymbolAddress((void**)&wp, g_wp);

    static bool attr_done = false;
    if (!attr_done) {
        cudaFuncSetAttribute(swsa5, cudaFuncAttributeMaxDynamicSharedMemorySize, SWSA5_SMEM);
        attr_done = true;
    }

    const int ln_blocks = NN * HWSZ / 256;

    // ---- pack all GEMM weights (one launch) ----
    wpack_all<<<(WP_TOTAL + 255) / 256, 256>>>(s_cin_w, s_cout_w, m_qkv_w, m_proj_w,
                                               g_in_w, g_out_w, wp);

    // ===== SWSA branch =====
    ln_p<<<ln_blocks, 256>>>(x, norm_w, norm_b, lnp);
    pconv5<32, 3, 128, true, false><<<dim3(128, 2, NN), 256>>>(
        lnp, wp + WP_SCIN, s_cin_b, nullptr, nullptr, bufBp, C3, nullptr, nullptr, nullptr);
    swsa5<<<NN * 256, 256, SWSA5_SMEM>>>(bufBp, s_dw_w, s_dw_b, s_rpb, lnp);
    // cout: xo = x + swsa, fused LN(xo) -> lnp2
    pconv5<32, 3, 64, false, true><<<dim3(64, 1, NN), 256>>>(
        lnp, wp + WP_SCOUT, s_cout_b, x, xo, nullptr, CCH, norm_w, norm_b, lnp2);

    // ===== MDTA branch =====
    pconv5<32, 1, 128, true, false><<<dim3(128, 2, NN), 256>>>(
        lnp2, wp + WP_MQKV, nullptr, nullptr, nullptr, bufBp, C3, nullptr, nullptr, nullptr);
    dw3x3_p<2><<<(NN * 96 * 4096 + 255) / 256, 256>>>(bufBp, m_dw_w, nullptr, bufAp, 96);
    mdta_gram_p<<<512, 256>>>(bufAp, part);
    mdta_gram_reduce<<<32, 256>>>(part, m_temp, attn);
    mdta_out_p<<<dim3(16, NN), 256>>>(bufAp, attn, lnp);
    // proj: xo = xo + mdta, fused LN(xo) -> lnp2
    pconv5<32, 1, 64, false, true><<<dim3(64, 1, NN), 256>>>(
        lnp, wp + WP_MPROJ, nullptr, xo, xo, nullptr, CCH, norm_w, norm_b, lnp2);

    // ===== GDFN branch =====
    pconv5<32, 1, 128, true, false><<<dim3(128, 3, NN), 256>>>(
        lnp2, wp + WP_GIN, g_in_b, nullptr, nullptr, bufAp, HID2, nullptr, nullptr, nullptr);
    gdfn_p<<<(NN * 85 * 4096 + 255) / 256, 256>>>(bufAp, g_d1_w, g_d1_b, g_d2_w, g_d2_b, bufBp);
    pconv5<85, 1, 64, false, false><<<dim3(64, 1, NN), 256>>>(
        bufBp, wp + WP_GOUT, g_out_b, xo, xo, nullptr, CCH, nullptr, nullptr, nullptr);
}

// round 10
// speedup vs baseline: 1.1070x; 1.1070x over previous
#include <cuda_runtime.h>
#include <cuda_bf16.h>
#include <math.h>
#include <stdint.h>

#define HWSZ 16384
#define WD 128
#define NN 8
#define CCH 64
#define C3 192
#define HIDC 170
#define HID2 340
#define NHEADS 4

// ---------------- scratch (device globals; allocation is banned) ----------------
__device__ uint32_t g_lnp[(size_t)NN * 32 * HWSZ];     // packed bf16 branch intermediate
__device__ uint32_t g_lnp2[(size_t)NN * 32 * HWSZ];    // packed bf16 LN output (fused epilogues)
__device__ uint32_t g_bufAp[(size_t)NN * 170 * HWSZ];
__device__ uint32_t g_bufBp[(size_t)NN * 96 * HWSZ];
__device__ float g_attn[NN * NHEADS * 16 * 16];
__device__ float g_part[512 * 288];
__device__ uint32_t g_wp[50176];

// weight-pack offsets (words)
#define WP_SCIN  0
#define WP_SCOUT 18432
#define WP_MQKV  24576
#define WP_MPROJ 30720
#define WP_GIN   32768
#define WP_GOUT  43648
#define WP_TOTAL 49280

// ---------------- helpers ----------------
__device__ __forceinline__ void mma_tf32(float4& d,
                                         uint32_t a0, uint32_t a1, uint32_t a2, uint32_t a3,
                                         uint32_t b0, uint32_t b1) {
    asm volatile(
        "mma.sync.aligned.m16n8k8.row.col.f32.tf32.tf32.f32 "
        "{%0,%1,%2,%3}, {%4,%5,%6,%7}, {%8,%9}, {%0,%1,%2,%3};\n"
        : "+f"(d.x), "+f"(d.y), "+f"(d.z), "+f"(d.w)
        : "r"(a0), "r"(a1), "r"(a2), "r"(a3), "r"(b0), "r"(b1));
}
__device__ __forceinline__ void mma_bf16(float4& d,
                                         uint32_t a0, uint32_t a1, uint32_t a2, uint32_t a3,
                                         uint32_t b0, uint32_t b1) {
    asm volatile(
        "mma.sync.aligned.m16n8k16.row.col.f32.bf16.bf16.f32 "
        "{%0,%1,%2,%3}, {%4,%5,%6,%7}, {%8,%9}, {%0,%1,%2,%3};\n"
        : "+f"(d.x), "+f"(d.y), "+f"(d.z), "+f"(d.w)
        : "r"(a0), "r"(a1), "r"(a2), "r"(a3), "r"(b0), "r"(b1));
}
__device__ __forceinline__ uint32_t pack_bf16(float lo, float hi) {
    __nv_bfloat162 h = __floats2bfloat162_rn(lo, hi);
    return *(uint32_t*)&h;
}
__device__ __forceinline__ float2 upk(uint32_t w) {
    __nv_bfloat162 h = *(__nv_bfloat162*)&w;
    return __bfloat1622float2(h);
}
__device__ __forceinline__ uint32_t hfma2_bf(uint32_t a, uint32_t b, uint32_t c) {
    __nv_bfloat162 r = __hfma2(*(__nv_bfloat162*)&a, *(__nv_bfloat162*)&b, *(__nv_bfloat162*)&c);
    return *(uint32_t*)&r;
}
__device__ __forceinline__ uint4 uz4(const uint32_t* p, bool valid) {
    return valid ? *(const uint4*)p : make_uint4(0u, 0u, 0u, 0u);
}

// ---------------- single fused weight pack ----------------
__device__ __forceinline__ uint32_t pack_one(const float* w, int m, int k2,
                                             int KC2, int TAPS, int KTOT2) {
    if (k2 >= KTOT2) return 0u;
    int KCfull = KC2 * 2;
    int i0, i1;
    if (TAPS == 1) { i0 = m * KCfull + 2 * k2; i1 = i0 + 1; }
    else {
        int dt = k2 / KC2, ic2 = k2 % KC2;
        i0 = (m * KCfull + 2 * ic2) * 3 + dt;
        i1 = (m * KCfull + 2 * ic2 + 1) * 3 + dt;
    }
    return pack_bf16(w[i0], w[i1]);
}

__global__ __launch_bounds__(256) void wpack_all(const float* __restrict__ scin,
                                                 const float* __restrict__ scout,
                                                 const float* __restrict__ mqkv,
                                                 const float* __restrict__ mproj,
                                                 const float* __restrict__ gin,
                                                 const float* __restrict__ gout,
                                                 uint32_t* __restrict__ dst) {
    int t = blockIdx.x * 256 + threadIdx.x;
    if (t >= WP_TOTAL) return;
    uint32_t v;
    if (t < WP_SCOUT) {
        int u = t - WP_SCIN;      v = pack_one(scin, u / 96, u % 96, 32, 3, 96);
    } else if (t < WP_MQKV) {
        int u = t - WP_SCOUT;     v = pack_one(scout, u / 96, u % 96, 32, 3, 96);
    } else if (t < WP_MPROJ) {
        int u = t - WP_MQKV;      v = pack_one(mqkv, u / 32, u % 32, 32, 1, 32);
    } else if (t < WP_GIN) {
        int u = t - WP_MPROJ;     v = pack_one(mproj, u / 32, u % 32, 32, 1, 32);
    } else if (t < WP_GOUT) {
        int u = t - WP_GIN;       v = pack_one(gin, u / 32, u % 32, 32, 1, 32);
    } else {
        int u = t - WP_GOUT;      v = pack_one(gout, u / 88, u % 88, 85, 1, 85);
    }
    dst[t] = v;
}

// ---------------- LayerNorm -> packed bf16 (branch 1 only) ----------------
__global__ __launch_bounds__(256) void ln_p(const float* __restrict__ x,
                                            const float* __restrict__ w,
                                            const float* __restrict__ b,
                                            uint32_t* __restrict__ outp) {
    int idx = blockIdx.x * 256 + threadIdx.x;
    int n = idx >> 14, hw = idx & (HWSZ - 1);
    const float* px = x + (size_t)n * CCH * HWSZ + hw;
    float v[CCH];
    float s = 0.f;
#pragma unroll
    for (int c = 0; c < CCH; c++) { v[c] = px[(size_t)c * HWSZ]; s += v[c]; }
    float mu = s * (1.f / CCH);
    float ss = 0.f;
#pragma unroll
    for (int c = 0; c < CCH; c++) { float d = v[c] - mu; ss = fmaf(d, d, ss); }
    float inv = rsqrtf(ss * (1.f / CCH) + 1e-5f);
    uint32_t* po = outp + (size_t)n * 32 * HWSZ + hw;
#pragma unroll
    for (int c2 = 0; c2 < 32; c2++) {
        float a = (v[2 * c2] - mu) * inv * w[2 * c2] + b[2 * c2];
        float c_ = (v[2 * c2 + 1] - mu) * inv * w[2 * c2 + 1] + b[2 * c2 + 1];
        po[(size_t)c2 * HWSZ] = pack_bf16(a, c_);
    }
}

// ---------------- bf16 tensor-core pointwise conv, cp.async double-buffered ----------------
template <int KC2, int TAPS, int MTILE, bool OUTBF, bool LNOUT>
__global__ __launch_bounds__(256, 2) void pconv5(const uint32_t* __restrict__ inp,
                                                 const uint32_t* __restrict__ wp,
                                                 const float* __restrict__ bias,
                                                 const float* __restrict__ resid,
                                                 float* __restrict__ outf,
                                                 uint32_t* __restrict__ outp, int M,
                                                 const float* __restrict__ normw,
                                                 const float* __restrict__ normb,
                                                 uint32_t* __restrict__ lnoutp) {
    constexpr int KTOT2 = KC2 * TAPS;
    constexpr int NCHUNK = (KTOT2 + 7) / 8;
    constexpr int KP2 = NCHUNK * 8;
    constexpr int PTILE = (MTILE == 64) ? 256 : 128;
    constexpr int XSW = PTILE + 8;
    constexpr int WSW = 12;
    constexpr int MW = MTILE / 32;
    __shared__ uint32_t sX[2][8 * XSW];
    __shared__ uint32_t sW[2][MTILE * WSW];
    __shared__ float lnS[2][256];
    __shared__ float lnQ[2][256];

    const int tid = threadIdx.x;
    const int lane = tid & 31, warp = tid >> 5;
    const int mw = warp % MW, pw = warp / MW;
    const int mbase = blockIdx.y * MTILE;
    const int pix0 = blockIdx.x * PTILE;
    const int n = blockIdx.z, b = n >> 2, t = n & 3;
    const int l3 = lane & 3, r = lane >> 2;

    float4 acc[2][8];
#pragma unroll
    for (int mt = 0; mt < 2; mt++)
#pragma unroll
        for (int j = 0; j < 8; j++) acc[mt][j] = make_float4(0.f, 0.f, 0.f, 0.f);

    auto stageX = [&](int c0, int bufi) {
#pragma unroll
        for (int i = tid; i < 2 * PTILE; i += 256) {
            int row = i / (PTILE / 4), p4 = (i % (PTILE / 4)) << 2;
            int k2 = c0 * 8 + row;
            const uint32_t* sp = inp;
            int sz = 0;
            if (k2 < KTOT2) {
                int ic2, tt;
                if (TAPS == 1) { ic2 = k2; tt = t; }
                else { int dt = k2 / KC2; ic2 = k2 - dt * KC2; tt = t + dt - 1; }
                if (tt >= 0 && tt < 4) {
                    sp = &inp[((size_t)(b * 4 + tt) * KC2 + ic2) * HWSZ + pix0 + p4];
                    sz = 16;
                }
            }
            uint32_t d = (uint32_t)__cvta_generic_to_shared(&sX[bufi][row * XSW + p4]);
            asm volatile("cp.async.cg.shared.global [%0],[%1],16,%2;\n"
                         :: "r"(d), "l"(sp), "r"(sz));
        }
    };
    auto stageW = [&](int c0, int bufi) {
#pragma unroll
        for (int i = tid; i < MTILE * 2; i += 256) {
            int m = i >> 1, q = i & 1;
            int gk2 = c0 * 8 + q * 4;
            int sz = (mbase + m < M) ? 16 : 0;
            const uint32_t* sp = (sz > 0) ? &wp[(size_t)(mbase + m) * KP2 + gk2] : wp;
            uint32_t d = (uint32_t)__cvta_generic_to_shared(&sW[bufi][m * WSW + q * 4]);
            asm volatile("cp.async.cg.shared.global [%0],[%1],16,%2;\n"
                         :: "r"(d), "l"(sp), "r"(sz));
        }
    };

    stageX(0, 0); stageW(0, 0);
    asm volatile("cp.async.commit_group;\n");
    int buf = 0;
    for (int c = 0; c < NCHUNK; c++) {
        if (c + 1 < NCHUNK) {
            stageX(c + 1, buf ^ 1); stageW(c + 1, buf ^ 1);
            asm volatile("cp.async.commit_group;\n");
            asm volatile("cp.async.wait_group 1;\n");
        } else {
            asm volatile("cp.async.wait_group 0;\n");
        }
        __syncthreads();
        const uint32_t* X = sX[buf];
        const uint32_t* W = sW[buf];
        const int ar = mw * 32 + r;
        uint32_t a[2][4];
#pragma unroll
        for (int mt = 0; mt < 2; mt++) {
            int wb = (ar + mt * 16) * WSW;
            a[mt][0] = W[wb + l3];
            a[mt][1] = W[wb + 8 * WSW + l3];
            a[mt][2] = W[wb + l3 + 4];
            a[mt][3] = W[wb + 8 * WSW + l3 + 4];
        }
        const int bc = pw * 64 + r;
#pragma unroll
        for (int nt = 0; nt < 8; nt++) {
            uint32_t b0 = X[l3 * XSW + bc + nt * 8];
            uint32_t b1 = X[(l3 + 4) * XSW + bc + nt * 8];
            mma_bf16(acc[0][nt], a[0][0], a[0][1], a[0][2], a[0][3], b0, b1);
            mma_bf16(acc[1][nt], a[1][0], a[1][1], a[1][2], a[1][3], b0, b1);
        }
        __syncthreads();
        buf ^= 1;
    }

    const int r0 = mw * 32 + r;
    const int cb = pw * 64 + (l3 << 1);

    if (LNOUT) {
        float bi[2][2], nw[2][2], nbv[2][2];
#pragma unroll
        for (int mt = 0; mt < 2; mt++)
#pragma unroll
            for (int half = 0; half < 2; half++) {
                int oc = r0 + mt * 16 + half * 8;
                bi[mt][half] = bias ? bias[oc] : 0.f;
                nw[mt][half] = normw[oc];
                nbv[mt][half] = normb[oc];
            }
#pragma unroll
        for (int j = 0; j < 8; j++) {
            int p0 = cb + j * 8;
            float s0 = 0.f, q0 = 0.f, s1 = 0.f, q1 = 0.f;
#pragma unroll
            for (int mt = 0; mt < 2; mt++)
#pragma unroll
                for (int half = 0; half < 2; half++) {
                    int oc = r0 + mt * 16 + half * 8;
                    size_t ob = ((size_t)n * 64 + oc) * HWSZ + pix0 + p0;
                    float vx = (half ? acc[mt][j].z : acc[mt][j].x) + bi[mt][half];
                    float vy = (half ? acc[mt][j].w : acc[mt][j].y) + bi[mt][half];
                    float2 rv = *(const float2*)&resid[ob];
                    vx += rv.x; vy += rv.y;
                    *(float2*)&outf[ob] = make_float2(vx, vy);
                    if (half) { acc[mt][j].z = vx; acc[mt][j].w = vy; }
                    else { acc[mt][j].x = vx; acc[mt][j].y = vy; }
                    s0 += vx; q0 = fmaf(vx, vx, q0);
                    s1 += vy; q1 = fmaf(vy, vy, q1);
                }
#pragma unroll
            for (int msk = 4; msk <= 16; msk <<= 1) {
                s0 += __shfl_xor_sync(0xffffffffu, s0, msk);
                q0 += __shfl_xor_sync(0xffffffffu, q0, msk);
                s1 += __shfl_xor_sync(0xffffffffu, s1, msk);
                q1 += __shfl_xor_sync(0xffffffffu, q1, msk);
            }
            if (r == 0) {
                lnS[mw][p0] = s0; lnQ[mw][p0] = q0;
                lnS[mw][p0 + 1] = s1; lnQ[mw][p0 + 1] = q1;
            }
        }
        __syncthreads();
#pragma unroll
        for (int j = 0; j < 8; j++) {
            int p0 = cb + j * 8;
            float m0 = (lnS[0][p0] + lnS[1][p0]) * (1.f / 64);
            float v0 = (lnQ[0][p0] + lnQ[1][p0]) * (1.f / 64) - m0 * m0;
            float i0 = rsqrtf(fmaxf(v0, 0.f) + 1e-5f);
            float m1 = (lnS[0][p0 + 1] + lnS[1][p0 + 1]) * (1.f / 64);
            float v1 = (lnQ[0][p0 + 1] + lnQ[1][p0 + 1]) * (1.f / 64) - m1 * m1;
            float i1 = rsqrtf(fmaxf(v1, 0.f) + 1e-5f);
#pragma unroll
            for (int mt = 0; mt < 2; mt++)
#pragma unroll
                for (int half = 0; half < 2; half++) {
                    int oc = r0 + mt * 16 + half * 8;
                    float vx = half ? acc[mt][j].z : acc[mt][j].x;
                    float vy = half ? acc[mt][j].w : acc[mt][j].y;
                    float nx = (vx - m0) * i0 * nw[mt][half] + nbv[mt][half];
                    float ny = (vy - m1) * i1 * nw[mt][half] + nbv[mt][half];
                    float qx = __shfl_down_sync(0xffffffffu, nx, 4);
                    float qy = __shfl_down_sync(0xffffffffu, ny, 4);
                    if (!(r & 1)) {
                        uint2 st;
                        st.x = pack_bf16(nx, qx);
                        st.y = pack_bf16(ny, qy);
                        *(uint2*)&lnoutp[((size_t)n * 32 + (oc >> 1)) * HWSZ + pix0 + p0] = st;
                    }
                }
        }
    } else if (OUTBF) {
        const int M2 = M >> 1;
#pragma unroll
        for (int mt = 0; mt < 2; mt++)
#pragma unroll
            for (int half = 0; half < 2; half++) {
                int oc = mbase + r0 + mt * 16 + half * 8;
                float bi = (bias && oc < M) ? bias[oc] : 0.f;
#pragma unroll
                for (int j = 0; j < 8; j++) {
                    float vx = (half ? acc[mt][j].z : acc[mt][j].x) + bi;
                    float vy = (half ? acc[mt][j].w : acc[mt][j].y) + bi;
                    float qx = __shfl_down_sync(0xffffffffu, vx, 4);
                    float qy = __shfl_down_sync(0xffffffffu, vy, 4);
                    if (!(r & 1) && oc < M) {
                        uint2 st;
                        st.x = pack_bf16(vx, qx);
                        st.y = pack_bf16(vy, qy);
                        *(uint2*)&outp[((size_t)n * M2 + (oc >> 1)) * HWSZ + pix0 + cb + j * 8] = st;
                    }
                }
            }
    } else {
#pragma unroll
        for (int mt = 0; mt < 2; mt++)
#pragma unroll
            for (int half = 0; half < 2; half++) {
                int oc = mbase + r0 + mt * 16 + half * 8;
                if (oc >= M) continue;
                float bi = bias ? bias[oc] : 0.f;
                size_t ob = ((size_t)n * M + oc) * HWSZ + pix0 + cb;
#pragma unroll
                for (int j = 0; j < 8; j++) {
                    float2 v = (half == 0)
                        ? make_float2(acc[mt][j].x + bi, acc[mt][j].y + bi)
                        : make_float2(acc[mt][j].z + bi, acc[mt][j].w + bi);
                    if (resid) {
                        float2 rv = *(const float2*)&resid[ob + j * 8];
                        v.x += rv.x; v.y += rv.y;
                    }
                    *(float2*)&outf[ob + j * 8] = v;
                }
            }
    }
}

// ---------------- depthwise 3x3 on packed bf16 (channel pairs) ----------------
template <int DIL>
__global__ __launch_bounds__(256) void dw3x3_p(const uint32_t* __restrict__ inp,
                                               const float* __restrict__ w,
                                               const float* __restrict__ bias,
                                               uint32_t* __restrict__ outp, int CH2) {
    size_t idx = (size_t)blockIdx.x * 256 + threadIdx.x;
    size_t tot = (size_t)NN * CH2 * 4096;
    if (idx >= tot) return;
    int q = (int)(idx & 4095);
    int nc2 = (int)(idx >> 12);
    int c2 = nc2 % CH2;
    int h = q >> 5, x4 = (q & 31) << 2;
    const uint32_t* src = inp + (size_t)nc2 * HWSZ;
    float wl[9], wh[9];
#pragma unroll
    for (int i = 0; i < 9; i++) {
        wl[i] = w[(2 * c2) * 9 + i];
        wh[i] = w[(2 * c2 + 1) * 9 + i];
    }
    float bl = bias ? bias[2 * c2] : 0.f;
    float bh = bias ? bias[2 * c2 + 1] : 0.f;
    float al[4] = {bl, bl, bl, bl}, ah[4] = {bh, bh, bh, bh};
#pragma unroll
    for (int ki = 0; ki < 3; ki++) {
        int hh = h + (ki - 1) * DIL;
        if ((unsigned)hh >= 128u) continue;
        const uint32_t* row = src + hh * WD;
        uint32_t wbuf[12];
        *(uint4*)&wbuf[0] = uz4(row + x4 - 4, x4 >= 4);
        *(uint4*)&wbuf[4] = *(const uint4*)(row + x4);
        *(uint4*)&wbuf[8] = uz4(row + x4 + 4, x4 < 124);
        float flo[12], fhi[12];
#pragma unroll
        for (int i = 0; i < 12; i++) { float2 f = upk(wbuf[i]); flo[i] = f.x; fhi[i] = f.y; }
#pragma unroll
        for (int kj = 0; kj < 3; kj++) {
            float wvl = wl[ki * 3 + kj], wvh = wh[ki * 3 + kj];
            int off = 4 + (kj - 1) * DIL;
#pragma unroll
            for (int p = 0; p < 4; p++) {
                al[p] = fmaf(flo[off + p], wvl, al[p]);
                ah[p] = fmaf(fhi[off + p], wvh, ah[p]);
            }
        }
    }
    uint4 st;
    st.x = pack_bf16(al[0], ah[0]); st.y = pack_bf16(al[1], ah[1]);
    st.z = pack_bf16(al[2], ah[2]); st.w = pack_bf16(al[3], ah[3]);
    *(uint4*)&outp[(size_t)nc2 * HWSZ + q * 4] = st;
}

// ---------------- SWSA window attention (packed bf16 in/out, tensor cores) ----------------
__global__ __launch_bounds__(256) void swsa4p(const uint32_t* __restrict__ qkvp,
                                              const float* __restrict__ rpb,
                                              uint32_t* __restrict__ outp) {
    __shared__ float qsh[4 * 64 * 17];     // Q fp32 [head][q][d] x0.25 ; reused as osh [c][68]
    __shared__ float kshB[4 * 16 * 68];    // K fp32 [d][col]
    __shared__ uint32_t vsh[4 * 32 * 17];  // V bf16x2 pixel-pairs [head][k2][d]
    __shared__ float bsh4[4 * 225];

    const int tid = threadIdx.x;
    const int lane = tid & 31, warp = tid >> 5;
    const int n = blockIdx.x >> 8;
    const int wrem = blockIdx.x & 255;
    const int wbase = ((wrem >> 4) * 8) * WD + (wrem & 15) * 8;
    const size_t nb = (size_t)n * 96 * HWSZ;

    for (int i = tid; i < 512; i += 256) {
        int c2 = i >> 4, q4 = i & 15;
        int q0 = q4 * 4;
        int goff = wbase + (q4 >> 1) * WD + (q4 & 1) * 4;
        int head = c2 >> 3;
        int d0 = (c2 & 7) * 2, d1 = d0 + 1;
        uint4 Qw = *(const uint4*)&qkvp[nb + (size_t)c2 * HWSZ + goff];
        uint4 Kw = *(const uint4*)&qkvp[nb + (size_t)(32 + c2) * HWSZ + goff];
        uint4 Vw = *(const uint4*)&qkvp[nb + (size_t)(64 + c2) * HWSZ + goff];
        const uint32_t* qw = &Qw.x;
        const uint32_t* kw = &Kw.x;
#pragma unroll
        for (int j = 0; j < 4; j++) {
            float2 fq = upk(qw[j]);
            qsh[(head * 64 + q0 + j) * 17 + d0] = fq.x * 0.25f;
            qsh[(head * 64 + q0 + j) * 17 + d1] = fq.y * 0.25f;
            float2 fk = upk(kw[j]);
            kshB[(head * 16 + d0) * 68 + q0 + j] = fk.x;
            kshB[(head * 16 + d1) * 68 + q0 + j] = fk.y;
        }
        int k2a = q4 * 2, k2b = k2a + 1;
        vsh[(head * 32 + k2a) * 17 + d0] = (Vw.x & 0xFFFFu) | (Vw.y << 16);
        vsh[(head * 32 + k2b) * 17 + d0] = (Vw.z & 0xFFFFu) | (Vw.w << 16);
        vsh[(head * 32 + k2a) * 17 + d1] = (Vw.x >> 16) | (Vw.y & 0xFFFF0000u);
        vsh[(head * 32 + k2b) * 17 + d1] = (Vw.z >> 16) | (Vw.w & 0xFFFF0000u);
    }
    for (int i = tid; i < 900; i += 256) bsh4[(i & 3) * 225 + (i >> 2)] = rpb[i];
    __syncthreads();

    const int head = warp >> 1;
    const int qbase = (warp & 1) * 32;
    const int r = lane >> 2;
    const int l3 = lane & 3;
    const int kj2 = l3 * 2;

    // ---- QK^T (tf32) ----
    float4 S[2][8];
#pragma unroll
    for (int mt = 0; mt < 2; mt++)
#pragma unroll
        for (int nt = 0; nt < 8; nt++) S[mt][nt] = make_float4(0.f, 0.f, 0.f, 0.f);
    const float* Q = &qsh[head * 64 * 17];
    const float* K = &kshB[head * 16 * 68];
#pragma unroll
    for (int kb = 0; kb < 16; kb += 8) {
        const int kc = kb + l3;
        uint32_t a[2][4];
#pragma unroll
        for (int mt = 0; mt < 2; mt++) {
            int ar = qbase + mt * 16 + r;
            a[mt][0] = __float_as_uint(Q[ar * 17 + kc]);
            a[mt][1] = __float_as_uint(Q[(ar + 8) * 17 + kc]);
            a[mt][2] = __float_as_uint(Q[ar * 17 + kc + 4]);
            a[mt][3] = __float_as_uint(Q[(ar + 8) * 17 + kc + 4]);
        }
#pragma unroll
        for (int nt = 0; nt < 8; nt++) {
            uint32_t b0 = __float_as_uint(K[(kb + l3) * 68 + nt * 8 + r]);
            uint32_t b1 = __float_as_uint(K[(kb + 4 + l3) * 68 + nt * 8 + r]);
            mma_tf32(S[0][nt], a[0][0], a[0][1], a[0][2], a[0][3], b0, b1);
            mma_tf32(S[1][nt], a[1][0], a[1][1], a[1][2], a[1][3], b0, b1);
        }
    }

    // ---- bias + exp + relu^2 ----
    int Aq[2][2];
#pragma unroll
    for (int mt = 0; mt < 2; mt++)
#pragma unroll
        for (int rh = 0; rh < 2; rh++) {
            int q = qbase + mt * 16 + r + rh * 8;
            Aq[mt][rh] = ((q >> 3) + 7) * 15 + (q & 7) + 7;
        }
    const float* bh = &bsh4[head * 225];
    float den[2][2] = {{0.f, 0.f}, {0.f, 0.f}};
    uint32_t eb[2][8][2], ub[2][8][2];
#pragma unroll
    for (int mt = 0; mt < 2; mt++)
#pragma unroll
        for (int nt = 0; nt < 8; nt++) {
            int bc = nt * 15 + kj2;
            int i0 = Aq[mt][0] - bc;
            int i1 = Aq[mt][1] - bc;
            float4 s = S[mt][nt];
            float s0 = s.x + bh[i0], s1 = s.y + bh[i0 - 1];
            float s2 = s.z + bh[i1], s3 = s.w + bh[i1 - 1];
            float e0 = __expf(s0), e1 = __expf(s1), e2 = __expf(s2), e3 = __expf(s3);
            den[mt][0] += e0 + e1;
            den[mt][1] += e2 + e3;
            eb[mt][nt][0] = pack_bf16(e0, e1);
            eb[mt][nt][1] = pack_bf16(e2, e3);
            float u0 = fmaxf(s0, 0.f); u0 = 0.75f * u0 * u0;
            float u1 = fmaxf(s1, 0.f); u1 = 0.75f * u1 * u1;
            float u2 = fmaxf(s2, 0.f); u2 = 0.75f * u2 * u2;
            float u3 = fmaxf(s3, 0.f); u3 = 0.75f * u3 * u3;
            ub[mt][nt][0] = pack_bf16(u0, u1);
            ub[mt][nt][1] = pack_bf16(u2, u3);
        }
    uint32_t w2[2][2];
#pragma unroll
    for (int mt = 0; mt < 2; mt++)
#pragma unroll
        for (int rh = 0; rh < 2; rh++) {
            float dv = den[mt][rh];
            dv += __shfl_xor_sync(0xffffffffu, dv, 1);
            dv += __shfl_xor_sync(0xffffffffu, dv, 2);
            float wsm = 0.25f / dv;
            w2[mt][rh] = pack_bf16(wsm, wsm);
        }

    // ---- PV (bf16, C->A fragment reuse) ----
    float4 O[2][2];
#pragma unroll
    for (int mt = 0; mt < 2; mt++)
#pragma unroll
        for (int v = 0; v < 2; v++) O[mt][v] = make_float4(0.f, 0.f, 0.f, 0.f);
    const uint32_t* V = &vsh[head * 32 * 17];
#pragma unroll
    for (int mt = 0; mt < 2; mt++)
#pragma unroll
        for (int t = 0; t < 4; t++) {
            uint32_t a0 = hfma2_bf(eb[mt][2 * t][0], w2[mt][0], ub[mt][2 * t][0]);
            uint32_t a1 = hfma2_bf(eb[mt][2 * t][1], w2[mt][1], ub[mt][2 * t][1]);
            uint32_t a2 = hfma2_bf(eb[mt][2 * t + 1][0], w2[mt][0], ub[mt][2 * t + 1][0]);
            uint32_t a3 = hfma2_bf(eb[mt][2 * t + 1][1], w2[mt][1], ub[mt][2 * t + 1][1]);
#pragma unroll
            for (int v = 0; v < 2; v++) {
                uint32_t b0 = V[(t * 8 + l3) * 17 + v * 8 + r];
                uint32_t b1 = V[(t * 8 + 4 + l3) * 17 + v * 8 + r];
                mma_bf16(O[mt][v], a0, a1, a2, a3, b0, b1);
            }
        }

    // ---- stage output + packed store ----
    __syncthreads();
    float* osh = qsh;
#pragma unroll
    for (int mt = 0; mt < 2; mt++)
#pragma unroll
        for (int v = 0; v < 2; v++) {
            int qrow = qbase + mt * 16 + r;
            int c0 = head * 16 + v * 8 + kj2;
            osh[c0 * 68 + qrow] = O[mt][v].x;
            osh[(c0 + 1) * 68 + qrow] = O[mt][v].y;
            osh[c0 * 68 + qrow + 8] = O[mt][v].z;
            osh[(c0 + 1) * 68 + qrow + 8] = O[mt][v].w;
        }
    __syncthreads();
    for (int i = tid; i < 512; i += 256) {
        int c2 = i >> 4, q4 = i & 15;
        int q0 = q4 * 4;
        int goff = wbase + (q4 >> 1) * WD + (q4 & 1) * 4;
        const float* lo = &osh[(2 * c2) * 68 + q0];
        const float* hi = &osh[(2 * c2 + 1) * 68 + q0];
        uint4 st;
        st.x = pack_bf16(lo[0], hi[0]); st.y = pack_bf16(lo[1], hi[1]);
        st.z = pack_bf16(lo[2], hi[2]); st.w = pack_bf16(lo[3], hi[3]);
        *(uint4*)&outp[((size_t)n * 32 + c2) * HWSZ + goff] = st;
    }
}

// ---------------- MDTA gram partials (packed input) ----------------
__global__ __launch_bounds__(256) void mdta_gram_p(const uint32_t* __restrict__ qkvp,
                                                   float* __restrict__ part) {
    int blk = blockIdx.x;
    int seg = blk & 15;
    int nh = blk >> 4;
    int n = nh >> 2, head = nh & 3;
    int c = threadIdx.x >> 4, d = threadIdx.x & 15;
    __shared__ float qsh[16 * 129];
    __shared__ float ksh2[16 * 129];
    float acc = 0.f, qq = 0.f, kk2 = 0.f;
    const uint32_t* qb = qkvp + ((size_t)n * 96 + head * 8) * HWSZ;
    const uint32_t* kb = qkvp + ((size_t)n * 96 + 32 + head * 8) * HWSZ;
    int base0 = seg * 1024;
    for (int it = 0; it < 8; it++) {
        int base = base0 + it * 128;
        for (int i = threadIdx.x; i < 1024; i += 256) {
            int cc2 = i >> 7, j = i & 127;
            float2 fq = upk(qb[(size_t)cc2 * HWSZ + base + j]);
            qsh[(2 * cc2) * 129 + j] = fq.x;
            qsh[(2 * cc2 + 1) * 129 + j] = fq.y;
            float2 fk = upk(kb[(size_t)cc2 * HWSZ + base + j]);
            ksh2[(2 * cc2) * 129 + j] = fk.x;
            ksh2[(2 * cc2 + 1) * 129 + j] = fk.y;
        }
        __syncthreads();
#pragma unroll 8
        for (int j = 0; j < 128; j++) {
            float qv = qsh[c * 129 + j];
            float kv = ksh2[d * 129 + j];
            acc = fmaf(qv, kv, acc);
            if (d == 0) qq = fmaf(qv, qv, qq);
            if (c == 0) kk2 = fmaf(kv, kv, kk2);
        }
        __syncthreads();
    }
    float* pb = part + (size_t)blk * 288;
    pb[c * 16 + d] = acc;
    if (d == 0) pb[256 + c] = qq;
    if (c == 0) pb[272 + d] = kk2;
}

__global__ __launch_bounds__(256) void mdta_gram_reduce(const float* __restrict__ part,
                                                        const float* __restrict__ temp,
                                                        float* __restrict__ attn_out) {
    int nh = blockIdx.x;
    int n = nh >> 2, head = nh & 3;
    int tid = threadIdx.x;
    __shared__ float gram[256];
    __shared__ float qn[16], kn[16];
    float g = 0.f;
    for (int s = 0; s < 16; s++) g += part[(size_t)(nh * 16 + s) * 288 + tid];
    gram[tid] = g;
    if (tid < 16) {
        float qq = 0.f;
        for (int s = 0; s < 16; s++) qq += part[(size_t)(nh * 16 + s) * 288 + 256 + tid];
        qn[tid] = sqrtf(qq);
    } else if (tid < 32) {
        float kk = 0.f;
        for (int s = 0; s < 16; s++) kk += part[(size_t)(nh * 16 + s) * 288 + 272 + (tid - 16)];
        kn[tid - 16] = sqrtf(kk);
    }
    __syncthreads();
    if (tid < 16) {
        int r = tid;
        float tp = temp[head];
        float iq = 1.f / fmaxf(qn[r], 1e-12f);
        float rowv[16];
        float mx = -1e30f;
#pragma unroll
        for (int j = 0; j < 16; j++) {
            float a = gram[r * 16 + j] * iq / fmaxf(kn[j], 1e-12f) * tp;
            rowv[j] = a;
            mx = fmaxf(mx, a);
        }
        float den = 0.f;
#pragma unroll
        for (int j = 0; j < 16; j++) { float e = __expf(rowv[j] - mx); rowv[j] = e; den += e; }
        float inv = 1.f / den;
#pragma unroll
        for (int j = 0; j < 16; j++)
            attn_out[(((size_t)n * NHEADS + head) * 16 + r) * 16 + j] = rowv[j] * inv;
    }
}

// ---------------- MDTA: out = attn @ v (packed in/out) ----------------
__global__ __launch_bounds__(256) void mdta_out_p(const uint32_t* __restrict__ qkvp,
                                                  const float* __restrict__ attn,
                                                  uint32_t* __restrict__ outp) {
    __shared__ float ash[NHEADS * 256];
    int n = blockIdx.y;
    for (int i = threadIdx.x; i < NHEADS * 256; i += 256)
        ash[i] = attn[(size_t)n * NHEADS * 256 + i];
    __syncthreads();
    int hw = (blockIdx.x * 256 + threadIdx.x) * 4;
#pragma unroll
    for (int head = 0; head < NHEADS; head++) {
        float vv[16][4];
        const uint32_t* vb = qkvp + ((size_t)n * 96 + 64 + head * 8) * HWSZ + hw;
#pragma unroll
        for (int d2 = 0; d2 < 8; d2++) {
            uint4 wv = *(const uint4*)(vb + (size_t)d2 * HWSZ);
            const uint32_t* ws = &wv.x;
#pragma unroll
            for (int p = 0; p < 4; p++) {
                float2 f = upk(ws[p]);
                vv[2 * d2][p] = f.x;
                vv[2 * d2 + 1][p] = f.y;
            }
        }
#pragma unroll
        for (int c2 = 0; c2 < 8; c2++) {
            float slo[4] = {0.f, 0.f, 0.f, 0.f}, shi[4] = {0.f, 0.f, 0.f, 0.f};
            const float* alo = &ash[(head * 16 + 2 * c2) * 16];
            const float* ahi = &ash[(head * 16 + 2 * c2 + 1) * 16];
#pragma unroll
            for (int d = 0; d < 16; d++) {
                float wl = alo[d], wh = ahi[d];
#pragma unroll
                for (int p = 0; p < 4; p++) {
                    slo[p] = fmaf(wl, vv[d][p], slo[p]);
                    shi[p] = fmaf(wh, vv[d][p], shi[p]);
                }
            }
            uint4 st;
            st.x = pack_bf16(slo[0], shi[0]); st.y = pack_bf16(slo[1], shi[1]);
            st.z = pack_bf16(slo[2], shi[2]); st.w = pack_bf16(slo[3], shi[3]);
            *(uint4*)&outp[((size_t)n * 32 + head * 8 + c2) * HWSZ + hw] = st;
        }
    }
}

// ---------------- GDFN depthwise + gelu gate (packed in/out) ----------------
__global__ __launch_bounds__(256) void gdfn_p(const uint32_t* __restrict__ inp,
                                              const float* __restrict__ w1,
                                              const float* __restrict__ b1,
                                              const float* __restrict__ w2,
                                              const float* __restrict__ b2,
                                              uint32_t* __restrict__ outp) {
    size_t idx = (size_t)blockIdx.x * 256 + threadIdx.x;
    size_t tot = (size_t)NN * 85 * 4096;
    if (idx >= tot) return;
    int q = (int)(idx & 4095);
    int nc2 = (int)(idx >> 12);
    int c2 = nc2 % 85, n = nc2 / 85;
    int h = q >> 5, x4 = (q & 31) << 2;
    const uint32_t* s1 = inp + ((size_t)n * 170 + c2) * HWSZ;
    const uint32_t* s2 = inp + ((size_t)n * 170 + 85 + c2) * HWSZ;
    float w1l[9], w1h[9], w2l[9], w2h[9];
#pragma unroll
    for (int i = 0; i < 9; i++) {
        w1l[i] = w1[(2 * c2) * 9 + i]; w1h[i] = w1[(2 * c2 + 1) * 9 + i];
        w2l[i] = w2[(2 * c2) * 9 + i]; w2h[i] = w2[(2 * c2 + 1) * 9 + i];
    }
    float bal = b1[2 * c2], bah = b1[2 * c2 + 1];
    float bbl = b2[2 * c2], bbh = b2[2 * c2 + 1];
    float al[4] = {bal, bal, bal, bal}, ah[4] = {bah, bah, bah, bah};
    float bl[4] = {bbl, bbl, bbl, bbl}, bh[4] = {bbh, bbh, bbh, bbh};
#pragma unroll
    for (int ki = 0; ki < 3; ki++) {
        int hh = h + (ki - 1);
        if ((unsigned)hh >= 128u) continue;
        const uint32_t* r1 = s1 + hh * WD;
        const uint32_t* r2 = s2 + hh * WD;
        uint32_t wb1[12], wb2[12];
        *(uint4*)&wb1[0] = uz4(r1 + x4 - 4, x4 >= 4);
        *(uint4*)&wb1[4] = *(const uint4*)(r1 + x4);
        *(uint4*)&wb1[8] = uz4(r1 + x4 + 4, x4 < 124);
        *(uint4*)&wb2[0] = uz4(r2 + x4 - 4, x4 >= 4);
        *(uint4*)&wb2[4] = *(const uint4*)(r2 + x4);
        *(uint4*)&wb2[8] = uz4(r2 + x4 + 4, x4 < 124);
        float f1l[12], f1h[12], f2l[12], f2h[12];
#pragma unroll
        for (int i = 0; i < 12; i++) {
            float2 fa = upk(wb1[i]); f1l[i] = fa.x; f1h[i] = fa.y;
            float2 fb = upk(wb2[i]); f2l[i] = fb.x; f2h[i] = fb.y;
        }
#pragma unroll
        for (int kj = 0; kj < 3; kj++) {
            int off = 4 + (kj - 1);
            float v1l = w1l[ki * 3 + kj], v1h = w1h[ki * 3 + kj];
            float v2l = w2l[ki * 3 + kj], v2h = w2h[ki * 3 + kj];
#pragma unroll
            for (int p = 0; p < 4; p++) {
                al[p] = fmaf(f1l[off + p], v1l, al[p]);
                ah[p] = fmaf(f1h[off + p], v1h, ah[p]);
                bl[p] = fmaf(f2l[off + p], v2l, bl[p]);
                bh[p] = fmaf(f2h[off + p], v2h, bh[p]);
            }
        }
    }
    uint4 st;
    uint32_t* sp = &st.x;
#pragma unroll
    for (int p = 0; p < 4; p++) {
        float gl = 0.5f * al[p] * (1.f + erff(al[p] * 0.70710678118654752f));
        float gh = 0.5f * ah[p] * (1.f + erff(ah[p] * 0.70710678118654752f));
        sp[p] = pack_bf16(gl * bl[p], gh * bh[p]);
    }
    *(uint4*)&outp[(size_t)nc2 * HWSZ + q * 4] = st;
}

// ---------------- launch ----------------
extern "C" void kernel_launch(void* const* d_in, const int* in_sizes, int n_in,
                              void* d_out, int out_size) {
    const float* x       = (const float*)d_in[0];
    const float* norm_w  = (const float*)d_in[1];
    const float* norm_b  = (const float*)d_in[2];
    const float* s_cin_w = (const float*)d_in[3];
    const float* s_cin_b = (const float*)d_in[4];
    const float* s_dw_w  = (const float*)d_in[5];
    const float* s_dw_b  = (const float*)d_in[6];
    const float* s_rpb   = (const float*)d_in[7];
    const float* s_cout_w= (const float*)d_in[8];
    const float* s_cout_b= (const float*)d_in[9];
    const float* m_qkv_w = (const float*)d_in[10];
    const float* m_dw_w  = (const float*)d_in[11];
    const float* m_proj_w= (const float*)d_in[12];
    const float* m_temp  = (const float*)d_in[13];
    const float* g_in_w  = (const float*)d_in[14];
    const float* g_in_b  = (const float*)d_in[15];
    const float* g_d1_w  = (const float*)d_in[16];
    const float* g_d1_b  = (const float*)d_in[17];
    const float* g_d2_w  = (const float*)d_in[18];
    const float* g_d2_b  = (const float*)d_in[19];
    const float* g_out_w = (const float*)d_in[20];
    const float* g_out_b = (const float*)d_in[21];
    float* xo = (float*)d_out;

    uint32_t *lnp, *lnp2, *bufAp, *bufBp, *wp;
    float *attn, *part;
    cudaGetSymbolAddress((void**)&lnp, g_lnp);
    cudaGetSymbolAddress((void**)&lnp2, g_lnp2);
    cudaGetSymbolAddress((void**)&bufAp, g_bufAp);
    cudaGetSymbolAddress((void**)&bufBp, g_bufBp);
    cudaGetSymbolAddress((void**)&attn, g_attn);
    cudaGetSymbolAddress((void**)&part, g_part);
    cudaGetSymbolAddress((void**)&wp, g_wp);

    const int ln_blocks = NN * HWSZ / 256;

    // ---- pack all GEMM weights (one launch) ----
    wpack_all<<<(WP_TOTAL + 255) / 256, 256>>>(s_cin_w, s_cout_w, m_qkv_w, m_proj_w,
                                               g_in_w, g_out_w, wp);

    // ===== SWSA branch =====
    ln_p<<<ln_blocks, 256>>>(x, norm_w, norm_b, lnp);
    pconv5<32, 3, 128, true, false><<<dim3(128, 2, NN), 256>>>(
        lnp, wp + WP_SCIN, s_cin_b, nullptr, nullptr, bufBp, C3, nullptr, nullptr, nullptr);
    dw3x3_p<1><<<(NN * 96 * 4096 + 255) / 256, 256>>>(bufBp, s_dw_w, s_dw_b, bufAp, 96);
    swsa4p<<<NN * 256, 256>>>(bufAp, s_rpb, lnp);
    // cout: xo = x + swsa, fused LN(xo) -> lnp2
    pconv5<32, 3, 64, false, true><<<dim3(64, 1, NN), 256>>>(
        lnp, wp + WP_SCOUT, s_cout_b, x, xo, nullptr, CCH, norm_w, norm_b, lnp2);

    // ===== MDTA branch =====
    pconv5<32, 1, 128, true, false><<<dim3(128, 2, NN), 256>>>(
        lnp2, wp + WP_MQKV, nullptr, nullptr, nullptr, bufBp, C3, nullptr, nullptr, nullptr);
    dw3x3_p<2><<<(NN * 96 * 4096 + 255) / 256, 256>>>(bufBp, m_dw_w, nullptr, bufAp, 96);
    mdta_gram_p<<<512, 256>>>(bufAp, part);
    mdta_gram_reduce<<<32, 256>>>(part, m_temp, attn);
    mdta_out_p<<<dim3(16, NN), 256>>>(bufAp, attn, lnp);
    // proj: xo = xo + mdta, fused LN(xo) -> lnp2
    pconv5<32, 1, 64, false, true><<<dim3(64, 1, NN), 256>>>(
        lnp, wp + WP_MPROJ, nullptr, xo, xo, nullptr, CCH, norm_w, norm_b, lnp2);

    // ===== GDFN branch =====
    pconv5<32, 1, 128, true, false><<<dim3(128, 3, NN), 256>>>(
        lnp2, wp + WP_GIN, g_in_b, nullptr, nullptr, bufAp, HID2, nullptr, nullptr, nullptr);
    gdfn_p<<<(NN * 85 * 4096 + 255) / 256, 256>>>(bufAp, g_d1_w, g_d1_b, g_d2_w, g_d2_b, bufBp);
    pconv5<85, 1, 64, false, false><<<dim3(64, 1, NN), 256>>>(
        bufBp, wp + WP_GOUT, g_out_b, xo, xo, nullptr, CCH, nullptr, nullptr, nullptr);
}

// round 13
// speedup vs baseline: 1.1665x; 1.0537x over previous
#include <cuda_runtime.h>
#include <cuda_bf16.h>
#include <math.h>
#include <stdint.h>

#define HWSZ 16384
#define WD 128
#define NN 8
#define CCH 64
#define C3 192
#define HIDC 170
#define HID2 340
#define NHEADS 4

// ---------------- scratch (device globals; allocation is banned) ----------------
__device__ uint32_t g_lnp[(size_t)NN * 32 * HWSZ];
__device__ uint32_t g_lnp2[(size_t)NN * 32 * HWSZ];
__device__ uint32_t g_bufAp[(size_t)NN * 170 * HWSZ];
__device__ uint32_t g_bufBp[(size_t)NN * 96 * HWSZ];
__device__ float g_attn[NN * NHEADS * 16 * 16];
__device__ float g_part[512 * 288];
__device__ uint32_t g_wp[50176];

// weight-pack offsets (words)
#define WP_SCIN  0
#define WP_SCOUT 18432
#define WP_MQKV  24576
#define WP_MPROJ 30720
#define WP_GIN   32768
#define WP_GOUT  43648
#define WP_TOTAL 49280

// ---------------- helpers ----------------
__device__ __forceinline__ void mma_tf32(float4& d,
                                         uint32_t a0, uint32_t a1, uint32_t a2, uint32_t a3,
                                         uint32_t b0, uint32_t b1) {
    asm volatile(
        "mma.sync.aligned.m16n8k8.row.col.f32.tf32.tf32.f32 "
        "{%0,%1,%2,%3}, {%4,%5,%6,%7}, {%8,%9}, {%0,%1,%2,%3};\n"
        : "+f"(d.x), "+f"(d.y), "+f"(d.z), "+f"(d.w)
        : "r"(a0), "r"(a1), "r"(a2), "r"(a3), "r"(b0), "r"(b1));
}
__device__ __forceinline__ void mma_bf16(float4& d,
                                         uint32_t a0, uint32_t a1, uint32_t a2, uint32_t a3,
                                         uint32_t b0, uint32_t b1) {
    asm volatile(
        "mma.sync.aligned.m16n8k16.row.col.f32.bf16.bf16.f32 "
        "{%0,%1,%2,%3}, {%4,%5,%6,%7}, {%8,%9}, {%0,%1,%2,%3};\n"
        : "+f"(d.x), "+f"(d.y), "+f"(d.z), "+f"(d.w)
        : "r"(a0), "r"(a1), "r"(a2), "r"(a3), "r"(b0), "r"(b1));
}
__device__ __forceinline__ uint32_t pack_bf16(float lo, float hi) {
    __nv_bfloat162 h = __floats2bfloat162_rn(lo, hi);
    return *(uint32_t*)&h;
}
__device__ __forceinline__ float2 upk(uint32_t w) {
    __nv_bfloat162 h = *(__nv_bfloat162*)&w;
    return __bfloat1622float2(h);
}
__device__ __forceinline__ uint32_t hfma2_bf(uint32_t a, uint32_t b, uint32_t c) {
    __nv_bfloat162 r = __hfma2(*(__nv_bfloat162*)&a, *(__nv_bfloat162*)&b, *(__nv_bfloat162*)&c);
    return *(uint32_t*)&r;
}
__device__ __forceinline__ uint4 uz4(const uint32_t* p, bool valid) {
    return valid ? *(const uint4*)p : make_uint4(0u, 0u, 0u, 0u);
}

// ---------------- single fused weight pack ----------------
__device__ __forceinline__ uint32_t pack_one(const float* w, int m, int k2,
                                             int KC2, int TAPS, int KTOT2) {
    if (k2 >= KTOT2) return 0u;
    int KCfull = KC2 * 2;
    int i0, i1;
    if (TAPS == 1) { i0 = m * KCfull + 2 * k2; i1 = i0 + 1; }
    else {
        int dt = k2 / KC2, ic2 = k2 % KC2;
        i0 = (m * KCfull + 2 * ic2) * 3 + dt;
        i1 = (m * KCfull + 2 * ic2 + 1) * 3 + dt;
    }
    return pack_bf16(w[i0], w[i1]);
}

__global__ __launch_bounds__(256) void wpack_all(const float* __restrict__ scin,
                                                 const float* __restrict__ scout,
                                                 const float* __restrict__ mqkv,
                                                 const float* __restrict__ mproj,
                                                 const float* __restrict__ gin,
                                                 const float* __restrict__ gout,
                                                 uint32_t* __restrict__ dst) {
    int t = blockIdx.x * 256 + threadIdx.x;
    if (t >= WP_TOTAL) return;
    uint32_t v;
    if (t < WP_SCOUT) {
        int u = t - WP_SCIN;      v = pack_one(scin, u / 96, u % 96, 32, 3, 96);
    } else if (t < WP_MQKV) {
        int u = t - WP_SCOUT;     v = pack_one(scout, u / 96, u % 96, 32, 3, 96);
    } else if (t < WP_MPROJ) {
        int u = t - WP_MQKV;      v = pack_one(mqkv, u / 32, u % 32, 32, 1, 32);
    } else if (t < WP_GIN) {
        int u = t - WP_MPROJ;     v = pack_one(mproj, u / 32, u % 32, 32, 1, 32);
    } else if (t < WP_GOUT) {
        int u = t - WP_GIN;       v = pack_one(gin, u / 32, u % 32, 32, 1, 32);
    } else {
        int u = t - WP_GOUT;      v = pack_one(gout, u / 88, u % 88, 85, 1, 85);
    }
    dst[t] = v;
}

// ---------------- LayerNorm -> packed bf16 (branch 1 only) ----------------
__global__ __launch_bounds__(256) void ln_p(const float* __restrict__ x,
                                            const float* __restrict__ w,
                                            const float* __restrict__ b,
                                            uint32_t* __restrict__ outp) {
    int idx = blockIdx.x * 256 + threadIdx.x;
    int n = idx >> 14, hw = idx & (HWSZ - 1);
    const float* px = x + (size_t)n * CCH * HWSZ + hw;
    float v[CCH];
    float s = 0.f;
#pragma unroll
    for (int c = 0; c < CCH; c++) { v[c] = px[(size_t)c * HWSZ]; s += v[c]; }
    float mu = s * (1.f / CCH);
    float ss = 0.f;
#pragma unroll
    for (int c = 0; c < CCH; c++) { float d = v[c] - mu; ss = fmaf(d, d, ss); }
    float inv = rsqrtf(ss * (1.f / CCH) + 1e-5f);
    uint32_t* po = outp + (size_t)n * 32 * HWSZ + hw;
#pragma unroll
    for (int c2 = 0; c2 < 32; c2++) {
        float a = (v[2 * c2] - mu) * inv * w[2 * c2] + b[2 * c2];
        float c_ = (v[2 * c2 + 1] - mu) * inv * w[2 * c2 + 1] + b[2 * c2 + 1];
        po[(size_t)c2 * HWSZ] = pack_bf16(a, c_);
    }
}

// ---------------- bf16 tensor-core pointwise conv, cp.async double-buffered ----------------
template <int KC2, int TAPS, int MTILE, bool OUTBF, bool LNOUT>
__global__ __launch_bounds__(256, 2) void pconv5(const uint32_t* __restrict__ inp,
                                                 const uint32_t* __restrict__ wp,
                                                 const float* __restrict__ bias,
                                                 const float* __restrict__ resid,
                                                 float* __restrict__ outf,
                                                 uint32_t* __restrict__ outp, int M,
                                                 const float* __restrict__ normw,
                                                 const float* __restrict__ normb,
                                                 uint32_t* __restrict__ lnoutp) {
    constexpr int KTOT2 = KC2 * TAPS;
    constexpr int NCHUNK = (KTOT2 + 7) / 8;
    constexpr int KP2 = NCHUNK * 8;
    constexpr int PTILE = (MTILE == 64) ? 256 : 128;
    constexpr int XSW = PTILE + 8;
    constexpr int WSW = 12;
    constexpr int MW = MTILE / 32;
    __shared__ uint32_t sX[2][8 * XSW];
    __shared__ uint32_t sW[2][MTILE * WSW];
    __shared__ float lnS[4][256];
    __shared__ float lnQ[4][256];

    const int tid = threadIdx.x;
    const int lane = tid & 31, warp = tid >> 5;
    const int mw = warp % MW, pw = warp / MW;
    const int mbase = blockIdx.y * MTILE;
    const int pix0 = blockIdx.x * PTILE;
    const int n = blockIdx.z, b = n >> 2, t = n & 3;
    const int l3 = lane & 3, r = lane >> 2;

    float4 acc[2][8];
#pragma unroll
    for (int mt = 0; mt < 2; mt++)
#pragma unroll
        for (int j = 0; j < 8; j++) acc[mt][j] = make_float4(0.f, 0.f, 0.f, 0.f);

    auto stageX = [&](int c0, int bufi) {
        for (int i = tid; i < 2 * PTILE; i += 256) {
            int row = i / (PTILE / 4), p4 = (i % (PTILE / 4)) << 2;
            int k2 = c0 * 8 + row;
            const uint32_t* sp = inp;
            int sz = 0;
            if (k2 < KTOT2) {
                int ic2, tt;
                if (TAPS == 1) { ic2 = k2; tt = t; }
                else { int dt = k2 / KC2; ic2 = k2 - dt * KC2; tt = t + dt - 1; }
                if (tt >= 0 && tt < 4) {
                    sp = &inp[((size_t)(b * 4 + tt) * KC2 + ic2) * HWSZ + pix0 + p4];
                    sz = 16;
                }
            }
            uint32_t d = (uint32_t)__cvta_generic_to_shared(&sX[bufi][row * XSW + p4]);
            asm volatile("cp.async.cg.shared.global [%0],[%1],16,%2;\n"
                         :: "r"(d), "l"(sp), "r"(sz));
        }
    };
    auto stageW = [&](int c0, int bufi) {
        for (int i = tid; i < MTILE * 2; i += 256) {
            int m = i >> 1, q = i & 1;
            int gk2 = c0 * 8 + q * 4;
            int sz = (mbase + m < M) ? 16 : 0;
            const uint32_t* sp = (sz > 0) ? &wp[(size_t)(mbase + m) * KP2 + gk2] : wp;
            uint32_t d = (uint32_t)__cvta_generic_to_shared(&sW[bufi][m * WSW + q * 4]);
            asm volatile("cp.async.cg.shared.global [%0],[%1],16,%2;\n"
                         :: "r"(d), "l"(sp), "r"(sz));
        }
    };

    stageX(0, 0); stageW(0, 0);
    asm volatile("cp.async.commit_group;\n");
    int buf = 0;
    for (int c = 0; c < NCHUNK; c++) {
        if (c + 1 < NCHUNK) {
            stageX(c + 1, buf ^ 1); stageW(c + 1, buf ^ 1);
            asm volatile("cp.async.commit_group;\n");
            asm volatile("cp.async.wait_group 1;\n");
        } else {
            asm volatile("cp.async.wait_group 0;\n");
        }
        __syncthreads();
        const uint32_t* X = sX[buf];
        const uint32_t* W = sW[buf];
        const int ar = mw * 32 + r;
        uint32_t a[2][4];
#pragma unroll
        for (int mt = 0; mt < 2; mt++) {
            int wb = (ar + mt * 16) * WSW;
            a[mt][0] = W[wb + l3];
            a[mt][1] = W[wb + 8 * WSW + l3];
            a[mt][2] = W[wb + l3 + 4];
            a[mt][3] = W[wb + 8 * WSW + l3 + 4];
        }
        const int bc = pw * 64 + r;
#pragma unroll
        for (int nt = 0; nt < 8; nt++) {
            uint32_t b0 = X[l3 * XSW + bc + nt * 8];
            uint32_t b1 = X[(l3 + 4) * XSW + bc + nt * 8];
            mma_bf16(acc[0][nt], a[0][0], a[0][1], a[0][2], a[0][3], b0, b1);
            mma_bf16(acc[1][nt], a[1][0], a[1][1], a[1][2], a[1][3], b0, b1);
        }
        __syncthreads();
        buf ^= 1;
    }

    const int r0 = mw * 32 + r;
    const int cb = pw * 64 + (l3 << 1);

    if (LNOUT) {
        float bi[2][2], nw[2][2], nbv[2][2];
#pragma unroll
        for (int mt = 0; mt < 2; mt++)
#pragma unroll
            for (int half = 0; half < 2; half++) {
                int oc = r0 + mt * 16 + half * 8;
                bi[mt][half] = bias ? bias[oc] : 0.f;
                nw[mt][half] = normw[oc];
                nbv[mt][half] = normb[oc];
            }
#pragma unroll
        for (int j = 0; j < 8; j++) {
            int p0 = cb + j * 8;
            float s0 = 0.f, q0 = 0.f, s1 = 0.f, q1 = 0.f;
#pragma unroll
            for (int mt = 0; mt < 2; mt++)
#pragma unroll
                for (int half = 0; half < 2; half++) {
                    int oc = r0 + mt * 16 + half * 8;
                    size_t ob = ((size_t)n * 64 + oc) * HWSZ + pix0 + p0;
                    float vx = (half ? acc[mt][j].z : acc[mt][j].x) + bi[mt][half];
                    float vy = (half ? acc[mt][j].w : acc[mt][j].y) + bi[mt][half];
                    float2 rv = *(const float2*)&resid[ob];
                    vx += rv.x; vy += rv.y;
                    *(float2*)&outf[ob] = make_float2(vx, vy);
                    if (half) { acc[mt][j].z = vx; acc[mt][j].w = vy; }
                    else { acc[mt][j].x = vx; acc[mt][j].y = vy; }
                    s0 += vx; q0 = fmaf(vx, vx, q0);
                    s1 += vy; q1 = fmaf(vy, vy, q1);
                }
#pragma unroll
            for (int msk = 4; msk <= 16; msk <<= 1) {
                s0 += __shfl_xor_sync(0xffffffffu, s0, msk);
                q0 += __shfl_xor_sync(0xffffffffu, q0, msk);
                s1 += __shfl_xor_sync(0xffffffffu, s1, msk);
                q1 += __shfl_xor_sync(0xffffffffu, q1, msk);
            }
            if (r == 0) {
                lnS[mw][p0] = s0; lnQ[mw][p0] = q0;
                lnS[mw][p0 + 1] = s1; lnQ[mw][p0 + 1] = q1;
            }
        }
        __syncthreads();
#pragma unroll
        for (int j = 0; j < 8; j++) {
            int p0 = cb + j * 8;
            float m0 = (lnS[0][p0] + lnS[1][p0]) * (1.f / 64);
            float v0 = (lnQ[0][p0] + lnQ[1][p0]) * (1.f / 64) - m0 * m0;
            float i0 = rsqrtf(fmaxf(v0, 0.f) + 1e-5f);
            float m1 = (lnS[0][p0 + 1] + lnS[1][p0 + 1]) * (1.f / 64);
            float v1 = (lnQ[0][p0 + 1] + lnQ[1][p0 + 1]) * (1.f / 64) - m1 * m1;
            float i1 = rsqrtf(fmaxf(v1, 0.f) + 1e-5f);
#pragma unroll
            for (int mt = 0; mt < 2; mt++)
#pragma unroll
                for (int half = 0; half < 2; half++) {
                    int oc = r0 + mt * 16 + half * 8;
                    float vx = half ? acc[mt][j].z : acc[mt][j].x;
                    float vy = half ? acc[mt][j].w : acc[mt][j].y;
                    float nx = (vx - m0) * i0 * nw[mt][half] + nbv[mt][half];
                    float ny = (vy - m1) * i1 * nw[mt][half] + nbv[mt][half];
                    float qx = __shfl_down_sync(0xffffffffu, nx, 4);
                    float qy = __shfl_down_sync(0xffffffffu, ny, 4);
                    if (!(r & 1)) {
                        uint2 st;
                        st.x = pack_bf16(nx, qx);
                        st.y = pack_bf16(ny, qy);
                        *(uint2*)&lnoutp[((size_t)n * 32 + (oc >> 1)) * HWSZ + pix0 + p0] = st;
                    }
                }
        }
    } else if (OUTBF) {
        const int M2 = M >> 1;
#pragma unroll
        for (int mt = 0; mt < 2; mt++)
#pragma unroll
            for (int half = 0; half < 2; half++) {
                int oc = mbase + r0 + mt * 16 + half * 8;
                float bi = (bias && oc < M) ? bias[oc] : 0.f;
#pragma unroll
                for (int j = 0; j < 8; j++) {
                    float vx = (half ? acc[mt][j].z : acc[mt][j].x) + bi;
                    float vy = (half ? acc[mt][j].w : acc[mt][j].y) + bi;
                    float qx = __shfl_down_sync(0xffffffffu, vx, 4);
                    float qy = __shfl_down_sync(0xffffffffu, vy, 4);
                    if (!(r & 1) && oc < M) {
                        uint2 st;
                        st.x = pack_bf16(vx, qx);
                        st.y = pack_bf16(vy, qy);
                        *(uint2*)&outp[((size_t)n * M2 + (oc >> 1)) * HWSZ + pix0 + cb + j * 8] = st;
                    }
                }
            }
    } else {
#pragma unroll
        for (int mt = 0; mt < 2; mt++)
#pragma unroll
            for (int half = 0; half < 2; half++) {
                int oc = mbase + r0 + mt * 16 + half * 8;
                if (oc >= M) continue;
                float bi = bias ? bias[oc] : 0.f;
                size_t ob = ((size_t)n * M + oc) * HWSZ + pix0 + cb;
#pragma unroll
                for (int j = 0; j < 8; j++) {
                    float2 v = (half == 0)
                        ? make_float2(acc[mt][j].x + bi, acc[mt][j].y + bi)
                        : make_float2(acc[mt][j].z + bi, acc[mt][j].w + bi);
                    if (resid) {
                        float2 rv = *(const float2*)&resid[ob + j * 8];
                        v.x += rv.x; v.y += rv.y;
                    }
                    *(float2*)&outf[ob + j * 8] = v;
                }
            }
    }
}

// ---------------- depthwise 3x3 on packed bf16: pure HFMA2 (no unpack) ----------------
template <int DIL>
__global__ __launch_bounds__(256) void dw3x3_h2(const uint32_t* __restrict__ inp,
                                                const float* __restrict__ w,
                                                const float* __restrict__ bias,
                                                uint32_t* __restrict__ outp, int CH2) {
    size_t idx = (size_t)blockIdx.x * 256 + threadIdx.x;
    size_t tot = (size_t)NN * CH2 * 4096;
    if (idx >= tot) return;
    int q = (int)(idx & 4095);
    int nc2 = (int)(idx >> 12);
    int c2 = nc2 % CH2;
    int h = q >> 5, x4 = (q & 31) << 2;
    const uint32_t* src = inp + (size_t)nc2 * HWSZ;
    uint32_t w2r[9];
#pragma unroll
    for (int i = 0; i < 9; i++)
        w2r[i] = pack_bf16(w[(2 * c2) * 9 + i], w[(2 * c2 + 1) * 9 + i]);
    uint32_t binit = bias ? pack_bf16(bias[2 * c2], bias[2 * c2 + 1]) : 0u;
    uint32_t acc2[4] = {binit, binit, binit, binit};
#pragma unroll
    for (int ki = 0; ki < 3; ki++) {
        int hh = h + (ki - 1) * DIL;
        if ((unsigned)hh >= 128u) continue;
        const uint32_t* row = src + hh * WD;
        uint32_t wbuf[12];
        *(uint4*)&wbuf[0] = uz4(row + x4 - 4, x4 >= 4);
        *(uint4*)&wbuf[4] = *(const uint4*)(row + x4);
        *(uint4*)&wbuf[8] = uz4(row + x4 + 4, x4 < 124);
#pragma unroll
        for (int kj = 0; kj < 3; kj++) {
            uint32_t wv = w2r[ki * 3 + kj];
            int off = 4 + (kj - 1) * DIL;
#pragma unroll
            for (int p = 0; p < 4; p++)
                acc2[p] = hfma2_bf(wbuf[off + p], wv, acc2[p]);
        }
    }
    uint4 st;
    st.x = acc2[0]; st.y = acc2[1]; st.z = acc2[2]; st.w = acc2[3];
    *(uint4*)&outp[(size_t)nc2 * HWSZ + q * 4] = st;
}

// ---------------- SWSA window attention (packed bf16 in/out, tensor cores) ----------------
__global__ __launch_bounds__(256) void swsa4p(const uint32_t* __restrict__ qkvp,
                                              const float* __restrict__ rpb,
                                              uint32_t* __restrict__ outp) {
    __shared__ float qsh[4 * 64 * 17];
    __shared__ float kshB[4 * 16 * 68];
    __shared__ uint32_t vsh[4 * 32 * 17];
    __shared__ float bsh4[4 * 225];

    const int tid = threadIdx.x;
    const int lane = tid & 31, warp = tid >> 5;
    const int n = blockIdx.x >> 8;
    const int wrem = blockIdx.x & 255;
    const int wbase = ((wrem >> 4) * 8) * WD + (wrem & 15) * 8;
    const size_t nb = (size_t)n * 96 * HWSZ;

    for (int i = tid; i < 512; i += 256) {
        int c2 = i >> 4, q4 = i & 15;
        int q0 = q4 * 4;
        int goff = wbase + (q4 >> 1) * WD + (q4 & 1) * 4;
        int head = c2 >> 3;
        int d0 = (c2 & 7) * 2, d1 = d0 + 1;
        uint4 Qw = *(const uint4*)&qkvp[nb + (size_t)c2 * HWSZ + goff];
        uint4 Kw = *(const uint4*)&qkvp[nb + (size_t)(32 + c2) * HWSZ + goff];
        uint4 Vw = *(const uint4*)&qkvp[nb + (size_t)(64 + c2) * HWSZ + goff];
        const uint32_t* qw = &Qw.x;
        const uint32_t* kw = &Kw.x;
#pragma unroll
        for (int j = 0; j < 4; j++) {
            float2 fq = upk(qw[j]);
            qsh[(head * 64 + q0 + j) * 17 + d0] = fq.x * 0.25f;
            qsh[(head * 64 + q0 + j) * 17 + d1] = fq.y * 0.25f;
            float2 fk = upk(kw[j]);
            kshB[(head * 16 + d0) * 68 + q0 + j] = fk.x;
            kshB[(head * 16 + d1) * 68 + q0 + j] = fk.y;
        }
        int k2a = q4 * 2, k2b = k2a + 1;
        vsh[(head * 32 + k2a) * 17 + d0] = (Vw.x & 0xFFFFu) | (Vw.y << 16);
        vsh[(head * 32 + k2b) * 17 + d0] = (Vw.z & 0xFFFFu) | (Vw.w << 16);
        vsh[(head * 32 + k2a) * 17 + d1] = (Vw.x >> 16) | (Vw.y & 0xFFFF0000u);
        vsh[(head * 32 + k2b) * 17 + d1] = (Vw.z >> 16) | (Vw.w & 0xFFFF0000u);
    }
    for (int i = tid; i < 900; i += 256) bsh4[(i & 3) * 225 + (i >> 2)] = rpb[i];
    __syncthreads();

    const int head = warp >> 1;
    const int qbase = (warp & 1) * 32;
    const int r = lane >> 2;
    const int l3 = lane & 3;
    const int kj2 = l3 * 2;

    float4 S[2][8];
#pragma unroll
    for (int mt = 0; mt < 2; mt++)
#pragma unroll
        for (int nt = 0; nt < 8; nt++) S[mt][nt] = make_float4(0.f, 0.f, 0.f, 0.f);
    const float* Q = &qsh[head * 64 * 17];
    const float* K = &kshB[head * 16 * 68];
#pragma unroll
    for (int kb = 0; kb < 16; kb += 8) {
        const int kc = kb + l3;
        uint32_t a[2][4];
#pragma unroll
        for (int mt = 0; mt < 2; mt++) {
            int ar = qbase + mt * 16 + r;
            a[mt][0] = __float_as_uint(Q[ar * 17 + kc]);
            a[mt][1] = __float_as_uint(Q[(ar + 8) * 17 + kc]);
            a[mt][2] = __float_as_uint(Q[ar * 17 + kc + 4]);
            a[mt][3] = __float_as_uint(Q[(ar + 8) * 17 + kc + 4]);
        }
#pragma unroll
        for (int nt = 0; nt < 8; nt++) {
            uint32_t b0 = __float_as_uint(K[(kb + l3) * 68 + nt * 8 + r]);
            uint32_t b1 = __float_as_uint(K[(kb + 4 + l3) * 68 + nt * 8 + r]);
            mma_tf32(S[0][nt], a[0][0], a[0][1], a[0][2], a[0][3], b0, b1);
            mma_tf32(S[1][nt], a[1][0], a[1][1], a[1][2], a[1][3], b0, b1);
        }
    }

    int Aq[2][2];
#pragma unroll
    for (int mt = 0; mt < 2; mt++)
#pragma unroll
        for (int rh = 0; rh < 2; rh++) {
            int q = qbase + mt * 16 + r + rh * 8;
            Aq[mt][rh] = ((q >> 3) + 7) * 15 + (q & 7) + 7;
        }
    const float* bh = &bsh4[head * 225];
    float den[2][2] = {{0.f, 0.f}, {0.f, 0.f}};
    uint32_t eb[2][8][2], ub[2][8][2];
#pragma unroll
    for (int mt = 0; mt < 2; mt++)
#pragma unroll
        for (int nt = 0; nt < 8; nt++) {
            int bc = nt * 15 + kj2;
            int i0 = Aq[mt][0] - bc;
            int i1 = Aq[mt][1] - bc;
            float4 s = S[mt][nt];
            float s0 = s.x + bh[i0], s1 = s.y + bh[i0 - 1];
            float s2 = s.z + bh[i1], s3 = s.w + bh[i1 - 1];
            float e0 = __expf(s0), e1 = __expf(s1), e2 = __expf(s2), e3 = __expf(s3);
            den[mt][0] += e0 + e1;
            den[mt][1] += e2 + e3;
            eb[mt][nt][0] = pack_bf16(e0, e1);
            eb[mt][nt][1] = pack_bf16(e2, e3);
            float u0 = fmaxf(s0, 0.f); u0 = 0.75f * u0 * u0;
            float u1 = fmaxf(s1, 0.f); u1 = 0.75f * u1 * u1;
            float u2 = fmaxf(s2, 0.f); u2 = 0.75f * u2 * u2;
            float u3 = fmaxf(s3, 0.f); u3 = 0.75f * u3 * u3;
            ub[mt][nt][0] = pack_bf16(u0, u1);
            ub[mt][nt][1] = pack_bf16(u2, u3);
        }
    uint32_t w2[2][2];
#pragma unroll
    for (int mt = 0; mt < 2; mt++)
#pragma unroll
        for (int rh = 0; rh < 2; rh++) {
            float dv = den[mt][rh];
            dv += __shfl_xor_sync(0xffffffffu, dv, 1);
            dv += __shfl_xor_sync(0xffffffffu, dv, 2);
            float wsm = 0.25f / dv;
            w2[mt][rh] = pack_bf16(wsm, wsm);
        }

    float4 O[2][2];
#pragma unroll
    for (int mt = 0; mt < 2; mt++)
#pragma unroll
        for (int v = 0; v < 2; v++) O[mt][v] = make_float4(0.f, 0.f, 0.f, 0.f);
    const uint32_t* V = &vsh[head * 32 * 17];
#pragma unroll
    for (int mt = 0; mt < 2; mt++)
#pragma unroll
        for (int t = 0; t < 4; t++) {
            uint32_t a0 = hfma2_bf(eb[mt][2 * t][0], w2[mt][0], ub[mt][2 * t][0]);
            uint32_t a1 = hfma2_bf(eb[mt][2 * t][1], w2[mt][1], ub[mt][2 * t][1]);
            uint32_t a2 = hfma2_bf(eb[mt][2 * t + 1][0], w2[mt][0], ub[mt][2 * t + 1][0]);
            uint32_t a3 = hfma2_bf(eb[mt][2 * t + 1][1], w2[mt][1], ub[mt][2 * t + 1][1]);
#pragma unroll
            for (int v = 0; v < 2; v++) {
                uint32_t b0 = V[(t * 8 + l3) * 17 + v * 8 + r];
                uint32_t b1 = V[(t * 8 + 4 + l3) * 17 + v * 8 + r];
                mma_bf16(O[mt][v], a0, a1, a2, a3, b0, b1);
            }
        }

    __syncthreads();
    float* osh = qsh;
#pragma unroll
    for (int mt = 0; mt < 2; mt++)
#pragma unroll
        for (int v = 0; v < 2; v++) {
            int qrow = qbase + mt * 16 + r;
            int c0 = head * 16 + v * 8 + kj2;
            osh[c0 * 68 + qrow] = O[mt][v].x;
            osh[(c0 + 1) * 68 + qrow] = O[mt][v].y;
            osh[c0 * 68 + qrow + 8] = O[mt][v].z;
            osh[(c0 + 1) * 68 + qrow + 8] = O[mt][v].w;
        }
    __syncthreads();
    for (int i = tid; i < 512; i += 256) {
        int c2 = i >> 4, q4 = i & 15;
        int q0 = q4 * 4;
        int goff = wbase + (q4 >> 1) * WD + (q4 & 1) * 4;
        const float* lo = &osh[(2 * c2) * 68 + q0];
        const float* hi = &osh[(2 * c2 + 1) * 68 + q0];
        uint4 st;
        st.x = pack_bf16(lo[0], hi[0]); st.y = pack_bf16(lo[1], hi[1]);
        st.z = pack_bf16(lo[2], hi[2]); st.w = pack_bf16(lo[3], hi[3]);
        *(uint4*)&outp[((size_t)n * 32 + c2) * HWSZ + goff] = st;
    }
}

// ---------------- MDTA gram partials (packed input) ----------------
__global__ __launch_bounds__(256) void mdta_gram_p(const uint32_t* __restrict__ qkvp,
                                                   float* __restrict__ part) {
    int blk = blockIdx.x;
    int seg = blk & 15;
    int nh = blk >> 4;
    int n = nh >> 2, head = nh & 3;
    int c = threadIdx.x >> 4, d = threadIdx.x & 15;
    __shared__ float qsh[16 * 129];
    __shared__ float ksh2[16 * 129];
    float acc = 0.f, qq = 0.f, kk2 = 0.f;
    const uint32_t* qb = qkvp + ((size_t)n * 96 + head * 8) * HWSZ;
    const uint32_t* kb = qkvp + ((size_t)n * 96 + 32 + head * 8) * HWSZ;
    int base0 = seg * 1024;
    for (int it = 0; it < 8; it++) {
        int base = base0 + it * 128;
        for (int i = threadIdx.x; i < 1024; i += 256) {
            int cc2 = i >> 7, j = i & 127;
            float2 fq = upk(qb[(size_t)cc2 * HWSZ + base + j]);
            qsh[(2 * cc2) * 129 + j] = fq.x;
            qsh[(2 * cc2 + 1) * 129 + j] = fq.y;
            float2 fk = upk(kb[(size_t)cc2 * HWSZ + base + j]);
            ksh2[(2 * cc2) * 129 + j] = fk.x;
            ksh2[(2 * cc2 + 1) * 129 + j] = fk.y;
        }
        __syncthreads();
#pragma unroll 8
        for (int j = 0; j < 128; j++) {
            float qv = qsh[c * 129 + j];
            float kv = ksh2[d * 129 + j];
            acc = fmaf(qv, kv, acc);
            if (d == 0) qq = fmaf(qv, qv, qq);
            if (c == 0) kk2 = fmaf(kv, kv, kk2);
        }
        __syncthreads();
    }
    float* pb = part + (size_t)blk * 288;
    pb[c * 16 + d] = acc;
    if (d == 0) pb[256 + c] = qq;
    if (c == 0) pb[272 + d] = kk2;
}

__global__ __launch_bounds__(256) void mdta_gram_reduce(const float* __restrict__ part,
                                                        const float* __restrict__ temp,
                                                        float* __restrict__ attn_out) {
    int nh = blockIdx.x;
    int n = nh >> 2, head = nh & 3;
    int tid = threadIdx.x;
    __shared__ float gram[256];
    __shared__ float qn[16], kn[16];
    float g = 0.f;
    for (int s = 0; s < 16; s++) g += part[(size_t)(nh * 16 + s) * 288 + tid];
    gram[tid] = g;
    if (tid < 16) {
        float qq = 0.f;
        for (int s = 0; s < 16; s++) qq += part[(size_t)(nh * 16 + s) * 288 + 256 + tid];
        qn[tid] = sqrtf(qq);
    } else if (tid < 32) {
        float kk = 0.f;
        for (int s = 0; s < 16; s++) kk += part[(size_t)(nh * 16 + s) * 288 + 272 + (tid - 16)];
        kn[tid - 16] = sqrtf(kk);
    }
    __syncthreads();
    if (tid < 16) {
        int r = tid;
        float tp = temp[head];
        float iq = 1.f / fmaxf(qn[r], 1e-12f);
        float rowv[16];
        float mx = -1e30f;
#pragma unroll
        for (int j = 0; j < 16; j++) {
            float a = gram[r * 16 + j] * iq / fmaxf(kn[j], 1e-12f) * tp;
            rowv[j] = a;
            mx = fmaxf(mx, a);
        }
        float den = 0.f;
#pragma unroll
        for (int j = 0; j < 16; j++) { float e = __expf(rowv[j] - mx); rowv[j] = e; den += e; }
        float inv = 1.f / den;
#pragma unroll
        for (int j = 0; j < 16; j++)
            attn_out[(((size_t)n * NHEADS + head) * 16 + r) * 16 + j] = rowv[j] * inv;
    }
}

// ---------------- MDTA: out = attn @ v (packed in/out) ----------------
__global__ __launch_bounds__(256) void mdta_out_p(const uint32_t* __restrict__ qkvp,
                                                  const float* __restrict__ attn,
                                                  uint32_t* __restrict__ outp) {
    __shared__ float ash[NHEADS * 256];
    int n = blockIdx.y;
    for (int i = threadIdx.x; i < NHEADS * 256; i += 256)
        ash[i] = attn[(size_t)n * NHEADS * 256 + i];
    __syncthreads();
    int hw = (blockIdx.x * 256 + threadIdx.x) * 4;
#pragma unroll
    for (int head = 0; head < NHEADS; head++) {
        float vv[16][4];
        const uint32_t* vb = qkvp + ((size_t)n * 96 + 64 + head * 8) * HWSZ + hw;
#pragma unroll
        for (int d2 = 0; d2 < 8; d2++) {
            uint4 wv = *(const uint4*)(vb + (size_t)d2 * HWSZ);
            const uint32_t* ws = &wv.x;
#pragma unroll
            for (int p = 0; p < 4; p++) {
                float2 f = upk(ws[p]);
                vv[2 * d2][p] = f.x;
                vv[2 * d2 + 1][p] = f.y;
            }
        }
#pragma unroll
        for (int c2 = 0; c2 < 8; c2++) {
            float slo[4] = {0.f, 0.f, 0.f, 0.f}, shi[4] = {0.f, 0.f, 0.f, 0.f};
            const float* alo = &ash[(head * 16 + 2 * c2) * 16];
            const float* ahi = &ash[(head * 16 + 2 * c2 + 1) * 16];
#pragma unroll
            for (int d = 0; d < 16; d++) {
                float wl = alo[d], wh = ahi[d];
#pragma unroll
                for (int p = 0; p < 4; p++) {
                    slo[p] = fmaf(wl, vv[d][p], slo[p]);
                    shi[p] = fmaf(wh, vv[d][p], shi[p]);
                }
            }
            uint4 st;
            st.x = pack_bf16(slo[0], shi[0]); st.y = pack_bf16(slo[1], shi[1]);
            st.z = pack_bf16(slo[2], shi[2]); st.w = pack_bf16(slo[3], shi[3]);
            *(uint4*)&outp[((size_t)n * 32 + head * 8 + c2) * HWSZ + hw] = st;
        }
    }
}

// ---------------- GDFN depthwise + gelu gate: HFMA2 conv, fp32 gelu ----------------
__global__ __launch_bounds__(256) void gdfn_h2(const uint32_t* __restrict__ inp,
                                               const float* __restrict__ w1,
                                               const float* __restrict__ b1,
                                               const float* __restrict__ w2,
                                               const float* __restrict__ b2,
                                               uint32_t* __restrict__ outp) {
    size_t idx = (size_t)blockIdx.x * 256 + threadIdx.x;
    size_t tot = (size_t)NN * 85 * 4096;
    if (idx >= tot) return;
    int q = (int)(idx & 4095);
    int nc2 = (int)(idx >> 12);
    int c2 = nc2 % 85, n = nc2 / 85;
    int h = q >> 5, x4 = (q & 31) << 2;
    const uint32_t* s1 = inp + ((size_t)n * 170 + c2) * HWSZ;
    const uint32_t* s2 = inp + ((size_t)n * 170 + 85 + c2) * HWSZ;
    uint32_t w21[9], w22[9];
#pragma unroll
    for (int i = 0; i < 9; i++) {
        w21[i] = pack_bf16(w1[(2 * c2) * 9 + i], w1[(2 * c2 + 1) * 9 + i]);
        w22[i] = pack_bf16(w2[(2 * c2) * 9 + i], w2[(2 * c2 + 1) * 9 + i]);
    }
    uint32_t ainit = pack_bf16(b1[2 * c2], b1[2 * c2 + 1]);
    uint32_t binit = pack_bf16(b2[2 * c2], b2[2 * c2 + 1]);
    uint32_t a2[4] = {ainit, ainit, ainit, ainit};
    uint32_t g2[4] = {binit, binit, binit, binit};
#pragma unroll
    for (int ki = 0; ki < 3; ki++) {
        int hh = h + (ki - 1);
        if ((unsigned)hh >= 128u) continue;
        const uint32_t* r1 = s1 + hh * WD;
        const uint32_t* r2 = s2 + hh * WD;
        uint32_t wb1[12], wb2[12];
        *(uint4*)&wb1[0] = uz4(r1 + x4 - 4, x4 >= 4);
        *(uint4*)&wb1[4] = *(const uint4*)(r1 + x4);
        *(uint4*)&wb1[8] = uz4(r1 + x4 + 4, x4 < 124);
        *(uint4*)&wb2[0] = uz4(r2 + x4 - 4, x4 >= 4);
        *(uint4*)&wb2[4] = *(const uint4*)(r2 + x4);
        *(uint4*)&wb2[8] = uz4(r2 + x4 + 4, x4 < 124);
#pragma unroll
        for (int kj = 0; kj < 3; kj++) {
            int off = 4 + (kj - 1);
            uint32_t v1 = w21[ki * 3 + kj];
            uint32_t v2 = w22[ki * 3 + kj];
#pragma unroll
            for (int p = 0; p < 4; p++) {
                a2[p] = hfma2_bf(wb1[off + p], v1, a2[p]);
                g2[p] = hfma2_bf(wb2[off + p], v2, g2[p]);
            }
        }
    }
    uint4 st;
    uint32_t* sp = &st.x;
#pragma unroll
    for (int p = 0; p < 4; p++) {
        float2 fa = upk(a2[p]);
        float2 fb = upk(g2[p]);
        float gl = 0.5f * fa.x * (1.f + erff(fa.x * 0.70710678118654752f));
        float gh = 0.5f * fa.y * (1.f + erff(fa.y * 0.70710678118654752f));
        sp[p] = pack_bf16(gl * fb.x, gh * fb.y);
    }
    *(uint4*)&outp[(size_t)nc2 * HWSZ + q * 4] = st;
}

// ---------------- launch ----------------
extern "C" void kernel_launch(void* const* d_in, const int* in_sizes, int n_in,
                              void* d_out, int out_size) {
    const float* x       = (const float*)d_in[0];
    const float* norm_w  = (const float*)d_in[1];
    const float* norm_b  = (const float*)d_in[2];
    const float* s_cin_w = (const float*)d_in[3];
    const float* s_cin_b = (const float*)d_in[4];
    const float* s_dw_w  = (const float*)d_in[5];
    const float* s_dw_b  = (const float*)d_in[6];
    const float* s_rpb   = (const float*)d_in[7];
    const float* s_cout_w= (const float*)d_in[8];
    const float* s_cout_b= (const float*)d_in[9];
    const float* m_qkv_w = (const float*)d_in[10];
    const float* m_dw_w  = (const float*)d_in[11];
    const float* m_proj_w= (const float*)d_in[12];
    const float* m_temp  = (const float*)d_in[13];
    const float* g_in_w  = (const float*)d_in[14];
    const float* g_in_b  = (const float*)d_in[15];
    const float* g_d1_w  = (const float*)d_in[16];
    const float* g_d1_b  = (const float*)d_in[17];
    const float* g_d2_w  = (const float*)d_in[18];
    const float* g_d2_b  = (const float*)d_in[19];
    const float* g_out_w = (const float*)d_in[20];
    const float* g_out_b = (const float*)d_in[21];
    float* xo = (float*)d_out;

    uint32_t *lnp, *lnp2, *bufAp, *bufBp, *wp;
    float *attn, *part;
    cudaGetSymbolAddress((void**)&lnp, g_lnp);
    cudaGetSymbolAddress((void**)&lnp2, g_lnp2);
    cudaGetSymbolAddress((void**)&bufAp, g_bufAp);
    cudaGetSymbolAddress((void**)&bufBp, g_bufBp);
    cudaGetSymbolAddress((void**)&attn, g_attn);
    cudaGetSymbolAddress((void**)&part, g_part);
    cudaGetSymbolAddress((void**)&wp, g_wp);

    const int ln_blocks = NN * HWSZ / 256;

    // ---- pack all GEMM weights (one launch) ----
    wpack_all<<<(WP_TOTAL + 255) / 256, 256>>>(s_cin_w, s_cout_w, m_qkv_w, m_proj_w,
                                               g_in_w, g_out_w, wp);

    // ===== SWSA branch =====
    ln_p<<<ln_blocks, 256>>>(x, norm_w, norm_b, lnp);
    pconv5<32, 3, 128, true, false><<<dim3(128, 2, NN), 256>>>(
        lnp, wp + WP_SCIN, s_cin_b, nullptr, nullptr, bufBp, C3, nullptr, nullptr, nullptr);
    dw3x3_h2<1><<<(NN * 96 * 4096 + 255) / 256, 256>>>(bufBp, s_dw_w, s_dw_b, bufAp, 96);
    swsa4p<<<NN * 256, 256>>>(bufAp, s_rpb, lnp);
    // cout: xo = x + swsa, fused LN(xo) -> lnp2
    pconv5<32, 3, 64, false, true><<<dim3(64, 1, NN), 256>>>(
        lnp, wp + WP_SCOUT, s_cout_b, x, xo, nullptr, CCH, norm_w, norm_b, lnp2);

    // ===== MDTA branch =====
    pconv5<32, 1, 128, true, false><<<dim3(128, 2, NN), 256>>>(
        lnp2, wp + WP_MQKV, nullptr, nullptr, nullptr, bufBp, C3, nullptr, nullptr, nullptr);
    dw3x3_h2<2><<<(NN * 96 * 4096 + 255) / 256, 256>>>(bufBp, m_dw_w, nullptr, bufAp, 96);
    mdta_gram_p<<<512, 256>>>(bufAp, part);
    mdta_gram_reduce<<<32, 256>>>(part, m_temp, attn);
    mdta_out_p<<<dim3(16, NN), 256>>>(bufAp, attn, lnp);
    // proj: xo = xo + mdta, fused LN(xo) -> lnp2
    pconv5<32, 1, 64, false, true><<<dim3(64, 1, NN), 256>>>(
        lnp, wp + WP_MPROJ, nullptr, xo, xo, nullptr, CCH, norm_w, norm_b, lnp2);

    // ===== GDFN branch =====
    pconv5<32, 1, 128, true, false><<<dim3(128, 3, NN), 256>>>(
        lnp2, wp + WP_GIN, g_in_b, nullptr, nullptr, bufAp, HID2, nullptr, nullptr, nullptr);
    gdfn_h2<<<(NN * 85 * 4096 + 255) / 256, 256>>>(bufAp, g_d1_w, g_d1_b, g_d2_w, g_d2_b, bufBp);
    pconv5<85, 1, 64, false, false><<<dim3(64, 1, NN), 256>>>(
        bufBp, wp + WP_GOUT, g_out_b, xo, xo, nullptr, CCH, nullptr, nullptr, nullptr);
}